// round 1
// baseline (speedup 1.0000x reference)
#include <cuda_runtime.h>
#include <cuda_bf16.h>
#include <math.h>

// ---------------------------------------------------------------------------
// WindowedAttention: x[B,6400,768] -> qkv GEMM -> 14x14 window attention
// (12 heads, hd=64, zero-padded to 84x84) -> merge -> proj GEMM + bias.
// Round 0: fp32 baseline. Stage 1/3 are tiled SGEMMs; stage 2 is one CTA per
// (window, head, batch) with K/V staged in dynamic smem and online softmax.
// ---------------------------------------------------------------------------

#define C_DIM    768
#define QKV_DIM  2304
#define B_SZ     8
#define H_IMG    80
#define W_IMG    80
#define NTOK     (H_IMG * W_IMG)     // 6400
#define WIN      14
#define NW_WIN   6                   // windows along W (84/14)
#define LWIN     36                  // 6*6 windows
#define NWTOK    (WIN * WIN)         // 196
#define NHEADS   12
#define HDIM     64
#define MTOT     (B_SZ * NTOK)       // 51200

// Scratch (allocation-free rule: __device__ globals)
__device__ float g_qkv[(size_t)B_SZ * NTOK * QKV_DIM];   // ~472 MB
__device__ float g_att[(size_t)B_SZ * NTOK * C_DIM];     // ~157 MB

// ---------------------------------------------------------------------------
// Tiled SGEMM: C[M,N] = A[M,K] @ B[K,N] (+ bias). BM=BN=128, BK=16, 8x8/thread.
// All dims here divide tiles exactly (M=51200, K=768, N in {2304, 768}).
// ---------------------------------------------------------------------------
template <int BM, int BN, int BK, int TM, int TN>
__global__ __launch_bounds__((BM / TM) * (BN / TN))
void sgemm_kernel(const float* __restrict__ A, const float* __restrict__ B,
                  const float* __restrict__ bias, float* __restrict__ C,
                  int M, int N, int K)
{
    constexpr int NT = (BM / TM) * (BN / TN);   // 256
    __shared__ float As[BK][BM];
    __shared__ float Bs[BK][BN];

    const int tid = threadIdx.x;
    const int tx  = tid % (BN / TN);            // 0..15
    const int ty  = tid / (BN / TN);            // 0..15
    const int rowBase = blockIdx.y * BM;
    const int colBase = blockIdx.x * BN;

    float acc[TM][TN];
#pragma unroll
    for (int i = 0; i < TM; i++)
#pragma unroll
        for (int j = 0; j < TN; j++) acc[i][j] = 0.f;

    for (int k0 = 0; k0 < K; k0 += BK) {
        // Load A tile (BM x BK), store transposed As[k][m]
#pragma unroll
        for (int it = 0; it < (BM * BK / 4) / NT; it++) {
            int e4 = tid + it * NT;
            int r = (e4 * 4) / BK;
            int c = (e4 * 4) % BK;
            float4 va = *(const float4*)&A[(size_t)(rowBase + r) * K + k0 + c];
            As[c + 0][r] = va.x;
            As[c + 1][r] = va.y;
            As[c + 2][r] = va.z;
            As[c + 3][r] = va.w;
        }
        // Load B tile (BK x BN)
#pragma unroll
        for (int it = 0; it < (BK * BN / 4) / NT; it++) {
            int e4 = tid + it * NT;
            int r = (e4 * 4) / BN;
            int c = (e4 * 4) % BN;
            *(float4*)&Bs[r][c] = *(const float4*)&B[(size_t)(k0 + r) * N + colBase + c];
        }
        __syncthreads();

#pragma unroll
        for (int kk = 0; kk < BK; kk++) {
            float a[TM], b[TN];
#pragma unroll
            for (int i = 0; i < TM; i++) a[i] = As[kk][ty * TM + i];
#pragma unroll
            for (int j = 0; j < TN; j++) b[j] = Bs[kk][tx * TN + j];
#pragma unroll
            for (int i = 0; i < TM; i++)
#pragma unroll
                for (int j = 0; j < TN; j++) acc[i][j] += a[i] * b[j];
        }
        __syncthreads();
    }

#pragma unroll
    for (int i = 0; i < TM; i++) {
        int row = rowBase + ty * TM + i;
#pragma unroll
        for (int j = 0; j < TN; j += 4) {
            int col = colBase + tx * TN + j;
            float4 v;
            v.x = acc[i][j + 0];
            v.y = acc[i][j + 1];
            v.z = acc[i][j + 2];
            v.w = acc[i][j + 3];
            if (bias != nullptr) {
                v.x += bias[col + 0];
                v.y += bias[col + 1];
                v.z += bias[col + 2];
                v.w += bias[col + 3];
            }
            *(float4*)&C[(size_t)row * N + col] = v;
        }
    }
}

// ---------------------------------------------------------------------------
// Window attention. Grid: (LWIN, NHEADS, B). Block: 256 threads.
// K/V [196,64] staged in dynamic smem (zero for padded positions, matching
// the reference's unmasked zero-pad). One query row per thread, online softmax.
// ---------------------------------------------------------------------------
__global__ __launch_bounds__(256)
void win_attn_kernel()
{
    extern __shared__ float smem[];
    float* sk = smem;                   // [196][64]
    float* sv = smem + NWTOK * HDIM;    // [196][64]

    const int l    = blockIdx.x;
    const int head = blockIdx.y;
    const int b    = blockIdx.z;
    const int wy   = l / NW_WIN;
    const int wx   = l % NW_WIN;
    const int tid  = threadIdx.x;

    // Cooperative K/V load (float4 granularity)
    const int NE4 = NWTOK * HDIM / 4;   // 3136
    for (int e4 = tid; e4 < NE4; e4 += 256) {
        int j  = e4 / (HDIM / 4);
        int d4 = (e4 % (HDIM / 4)) * 4;
        int r  = j / WIN;
        int c  = j % WIN;
        int hh = wy * WIN + r;
        int ww = wx * WIN + c;
        float4 kv = make_float4(0.f, 0.f, 0.f, 0.f);
        float4 vv = kv;
        if (hh < H_IMG && ww < W_IMG) {
            size_t base = ((size_t)(b * NTOK + hh * W_IMG + ww)) * QKV_DIM
                          + (size_t)head * HDIM + d4;
            kv = *(const float4*)&g_qkv[base + C_DIM];        // K (part 1)
            vv = *(const float4*)&g_qkv[base + 2 * C_DIM];    // V (part 2)
        }
        *(float4*)&sk[j * HDIM + d4] = kv;
        *(float4*)&sv[j * HDIM + d4] = vv;
    }
    __syncthreads();

    if (tid >= NWTOK) return;
    const int r  = tid / WIN;
    const int c  = tid % WIN;
    const int hh = wy * WIN + r;
    const int ww = wx * WIN + c;
    if (hh >= H_IMG || ww >= W_IMG) return;   // padded query: output discarded

    const size_t qbase = ((size_t)(b * NTOK + hh * W_IMG + ww)) * QKV_DIM
                         + (size_t)head * HDIM;
    float q[HDIM];
#pragma unroll
    for (int d4 = 0; d4 < HDIM; d4 += 4) {
        float4 t = *(const float4*)&g_qkv[qbase + d4];
        q[d4 + 0] = t.x; q[d4 + 1] = t.y; q[d4 + 2] = t.z; q[d4 + 3] = t.w;
    }

    float o[HDIM];
#pragma unroll
    for (int d = 0; d < HDIM; d++) o[d] = 0.f;
    float m = -1e30f, lsum = 0.f;
    const float scale = 0.125f;   // 64^-0.5

    for (int j = 0; j < NWTOK; j++) {
        const float* kj = &sk[j * HDIM];
        float s = 0.f;
#pragma unroll
        for (int d = 0; d < HDIM; d++) s += q[d] * kj[d];
        s *= scale;
        float mnew = fmaxf(m, s);
        float corr = __expf(m - mnew);
        float p    = __expf(s - mnew);
        lsum = lsum * corr + p;
        const float* vj = &sv[j * HDIM];
#pragma unroll
        for (int d = 0; d < HDIM; d++) o[d] = o[d] * corr + p * vj[d];
        m = mnew;
    }

    const float inv = 1.f / lsum;
    const size_t obase = ((size_t)(b * NTOK + hh * W_IMG + ww)) * C_DIM
                         + (size_t)head * HDIM;
#pragma unroll
    for (int d4 = 0; d4 < HDIM; d4 += 4) {
        float4 t;
        t.x = o[d4 + 0] * inv;
        t.y = o[d4 + 1] * inv;
        t.z = o[d4 + 2] * inv;
        t.w = o[d4 + 3] * inv;
        *(float4*)&g_att[obase + d4] = t;
    }
}

// ---------------------------------------------------------------------------
// Launch
// ---------------------------------------------------------------------------
extern "C" void kernel_launch(void* const* d_in, const int* in_sizes, int n_in,
                              void* d_out, int out_size)
{
    const float* x     = (const float*)d_in[0];   // [8, 6400, 768]
    const float* Wqkv  = (const float*)d_in[1];   // [768, 2304]
    const float* Wproj = (const float*)d_in[2];   // [768, 768]
    const float* bproj = (const float*)d_in[3];   // [768]
    float* out = (float*)d_out;                   // [8, 6400, 768]

    float* qkvp = nullptr;
    float* attp = nullptr;
    cudaGetSymbolAddress((void**)&qkvp, g_qkv);
    cudaGetSymbolAddress((void**)&attp, g_att);

    // Stage 1: qkv = x @ Wqkv   [51200,768] x [768,2304]
    {
        dim3 grid(QKV_DIM / 128, MTOT / 128);
        sgemm_kernel<128, 128, 16, 8, 8><<<grid, 256>>>(
            x, Wqkv, nullptr, qkvp, MTOT, QKV_DIM, C_DIM);
    }

    // Stage 2: windowed attention
    {
        const int smem_bytes = 2 * NWTOK * HDIM * (int)sizeof(float);  // 100352
        cudaFuncSetAttribute(win_attn_kernel,
                             cudaFuncAttributeMaxDynamicSharedMemorySize,
                             smem_bytes);
        dim3 grid(LWIN, NHEADS, B_SZ);
        win_attn_kernel<<<grid, 256, smem_bytes>>>();
    }

    // Stage 3: out = att @ Wproj + bproj   [51200,768] x [768,768]
    {
        dim3 grid(C_DIM / 128, MTOT / 128);
        sgemm_kernel<128, 128, 16, 8, 8><<<grid, 256>>>(
            attp, Wproj, bproj, out, MTOT, C_DIM, C_DIM);
    }
}

// round 4
// speedup vs baseline: 1.6596x; 1.6596x over previous
#include <cuda_runtime.h>
#include <cuda_bf16.h>
#include <math.h>
#include <stdint.h>

// ---------------------------------------------------------------------------
// WindowedAttention on GB300 (sm_103a chip, but ptxas target is base sm_103:
// tcgen05 is NOT available — R3 uses warp-level mma.sync bf16 tensor cores).
// Stages 1 & 3: bf16 hi/lo-split (3-term) HMMA GEMM, fp32 accumulate.
// ---------------------------------------------------------------------------

#define C_DIM    768
#define QKV_DIM  2304
#define B_SZ     8
#define H_IMG    80
#define W_IMG    80
#define NTOK     (H_IMG * W_IMG)     // 6400
#define WIN      14
#define NW_WIN   6
#define LWIN     36
#define NWTOK    (WIN * WIN)         // 196
#define NHEADS   12
#define HDIM     64
#define MTOT     (B_SZ * NTOK)       // 51200

// ---------------- scratch (__device__ globals: allocation-free rule) -------
__device__ float          g_qkv[(size_t)MTOT * QKV_DIM];        // fp32 qkv
__device__ __nv_bfloat16  g_xhi[(size_t)MTOT * C_DIM];
__device__ __nv_bfloat16  g_xlo[(size_t)MTOT * C_DIM];
__device__ __nv_bfloat16  g_wqkv_hi[(size_t)QKV_DIM * C_DIM];   // [N,K] K-major
__device__ __nv_bfloat16  g_wqkv_lo[(size_t)QKV_DIM * C_DIM];
__device__ __nv_bfloat16  g_wproj_hi[(size_t)C_DIM * C_DIM];    // [N,K] K-major
__device__ __nv_bfloat16  g_wproj_lo[(size_t)C_DIM * C_DIM];
__device__ __nv_bfloat16  g_atthi[(size_t)MTOT * C_DIM];
__device__ __nv_bfloat16  g_attlo[(size_t)MTOT * C_DIM];

extern __shared__ char smem_raw[];

// ---------------------------- PTX helpers ----------------------------------
__device__ __forceinline__ uint32_t smem_u32(const void* p) {
    uint32_t a;
    asm("{ .reg .u64 t; cvta.to.shared.u64 t, %1; cvt.u32.u64 %0, t; }"
        : "=r"(a) : "l"(p));
    return a;
}
__device__ __forceinline__ void cp16(uint32_t saddr, const void* g) {
    asm volatile("cp.async.cg.shared.global [%0], [%1], 16;" :: "r"(saddr), "l"(g));
}
__device__ __forceinline__ void cp_commit() { asm volatile("cp.async.commit_group;" ::: "memory"); }
template <int N> __device__ __forceinline__ void cp_wait() {
    asm volatile("cp.async.wait_group %0;" :: "n"(N) : "memory");
}
__device__ __forceinline__ void ldm_x4(uint32_t* r, uint32_t addr) {
    asm volatile("ldmatrix.sync.aligned.m8n8.x4.shared.b16 {%0,%1,%2,%3}, [%4];"
        : "=r"(r[0]), "=r"(r[1]), "=r"(r[2]), "=r"(r[3]) : "r"(addr));
}
__device__ __forceinline__ void mma16816(float* d, const uint32_t* a, const uint32_t* b) {
    asm volatile(
        "mma.sync.aligned.m16n8k16.row.col.f32.bf16.bf16.f32 "
        "{%0,%1,%2,%3}, {%4,%5,%6,%7}, {%8,%9}, {%0,%1,%2,%3};"
        : "+f"(d[0]), "+f"(d[1]), "+f"(d[2]), "+f"(d[3])
        : "r"(a[0]), "r"(a[1]), "r"(a[2]), "r"(a[3]), "r"(b[0]), "r"(b[1]));
}

// ---------------------------------------------------------------------------
// Warp-MMA GEMM: C[M,N] = (Ahi+Alo)[M,768] @ (Bhi+Blo)[N,768]^T (+ bias)
// A row-major [M,K], B K-major [N,K]. BM=BN=128, BK=32, 8 warps (2x4),
// warp tile 64x32. hi*hi + hi*lo + lo*hi (3 terms). cp.async double buffer.
// smem rows padded to 40 bf16 (80 B) -> conflict-free ldmatrix.
// ---------------------------------------------------------------------------
#define GBM 128
#define GBN 128
#define GBK 32
#define GNCH (768 / GBK)         // 24
#define ROWB 80                  // smem row stride bytes (32 bf16 + 8 pad)
#define OFF_AHI 0
#define OFF_ALO 10240
#define OFF_BHI 20480
#define OFF_BLO 30720
#define STG_SZ  40960
#define GEMM_SMEM (2 * STG_SZ)   // 81920

__device__ __forceinline__ void gemm_load_chunk(
    uint32_t buf,
    const __nv_bfloat16* __restrict__ Ahi, const __nv_bfloat16* __restrict__ Alo,
    const __nv_bfloat16* __restrict__ Bhi, const __nv_bfloat16* __restrict__ Blo,
    int rowBase, int colBase, int k0, int tid)
{
#pragma unroll
    for (int it = 0; it < 2; it++) {
        int t = tid + it * 256;           // 0..511
        int r = t >> 2;                   // row 0..127
        int c = t & 3;                    // 16B unit 0..3
        uint32_t soff = (uint32_t)(r * ROWB + c * 16);
        size_t ga = (size_t)(rowBase + r) * 768 + k0 + c * 8;
        size_t gb = (size_t)(colBase + r) * 768 + k0 + c * 8;
        cp16(buf + OFF_AHI + soff, Ahi + ga);
        cp16(buf + OFF_ALO + soff, Alo + ga);
        cp16(buf + OFF_BHI + soff, Bhi + gb);
        cp16(buf + OFF_BLO + soff, Blo + gb);
    }
    cp_commit();
}

__global__ void __launch_bounds__(256)
wmma_gemm(const __nv_bfloat16* __restrict__ Ahi, const __nv_bfloat16* __restrict__ Alo,
          const __nv_bfloat16* __restrict__ Bhi, const __nv_bfloat16* __restrict__ Blo,
          const float* __restrict__ bias, float* __restrict__ C, int N)
{
    const uint32_t sb = smem_u32(smem_raw);
    const int tid   = threadIdx.x;
    const int lane  = tid & 31;
    const int wid   = tid >> 5;
    const int warpM = wid >> 2;           // 0..1
    const int warpN = wid & 3;            // 0..3
    const int rowBase = blockIdx.y * GBM;
    const int colBase = blockIdx.x * GBN;

    float acc[4][4][4];
#pragma unroll
    for (int i = 0; i < 4; i++)
#pragma unroll
        for (int j = 0; j < 4; j++)
#pragma unroll
            for (int e = 0; e < 4; e++) acc[i][j][e] = 0.f;

    // per-lane ldmatrix address offsets (within a stage buffer)
    const uint32_t a_lane = (uint32_t)((warpM * 64 + (lane & 15)) * ROWB + (lane >> 4) * 16);
    const uint32_t b_lane = (uint32_t)((warpN * 32 + ((lane & 7) | ((lane >> 4) << 3))) * ROWB
                                       + ((lane >> 3) & 1) * 16);

    gemm_load_chunk(sb,          Ahi, Alo, Bhi, Blo, rowBase, colBase, 0,   tid);
    gemm_load_chunk(sb + STG_SZ, Ahi, Alo, Bhi, Blo, rowBase, colBase, GBK, tid);

    for (int ch = 0; ch < GNCH; ch++) {
        if (ch == GNCH - 1) cp_wait<0>(); else cp_wait<1>();
        __syncthreads();
        const uint32_t buf = sb + (uint32_t)(ch & 1) * STG_SZ;

#pragma unroll
        for (int k16 = 0; k16 < 2; k16++) {
            const uint32_t kb = (uint32_t)(k16 * 32);
            uint32_t ah[4][4], al[4][4];
#pragma unroll
            for (int mt = 0; mt < 4; mt++) {
                uint32_t ao = buf + a_lane + kb + (uint32_t)(mt * 16 * ROWB);
                ldm_x4(ah[mt], ao + OFF_AHI);
                ldm_x4(al[mt], ao + OFF_ALO);
            }
            uint32_t bh[2][4], bl[2][4];
#pragma unroll
            for (int half = 0; half < 2; half++) {
                uint32_t bo = buf + b_lane + kb + (uint32_t)(half * 16 * ROWB);
                ldm_x4(bh[half], bo + OFF_BHI);
                ldm_x4(bl[half], bo + OFF_BLO);
            }
#pragma unroll
            for (int mt = 0; mt < 4; mt++)
#pragma unroll
                for (int nt = 0; nt < 4; nt++) {
                    const uint32_t* bhf = &bh[nt >> 1][(nt & 1) * 2];
                    const uint32_t* blf = &bl[nt >> 1][(nt & 1) * 2];
                    mma16816(acc[mt][nt], ah[mt], bhf);
                    mma16816(acc[mt][nt], ah[mt], blf);
                    mma16816(acc[mt][nt], al[mt], bhf);
                }
        }
        __syncthreads();
        if (ch + 2 < GNCH)
            gemm_load_chunk(buf, Ahi, Alo, Bhi, Blo, rowBase, colBase,
                            (ch + 2) * GBK, tid);
    }

    // epilogue
#pragma unroll
    for (int mt = 0; mt < 4; mt++) {
        const int row0 = rowBase + warpM * 64 + mt * 16 + (lane >> 2);
#pragma unroll
        for (int nt = 0; nt < 4; nt++) {
            const int col = colBase + warpN * 32 + nt * 8 + (lane & 3) * 2;
            float b0 = 0.f, b1 = 0.f;
            if (bias != nullptr) { b0 = bias[col]; b1 = bias[col + 1]; }
            float2 v0 = make_float2(acc[mt][nt][0] + b0, acc[mt][nt][1] + b1);
            float2 v1 = make_float2(acc[mt][nt][2] + b0, acc[mt][nt][3] + b1);
            *(float2*)&C[(size_t)row0 * N + col]       = v0;
            *(float2*)&C[(size_t)(row0 + 8) * N + col] = v1;
        }
    }
}

// ---------------------------------------------------------------------------
// fp32 -> bf16 hi/lo elementwise split (for x)
// ---------------------------------------------------------------------------
__global__ void split_fp32(const float* __restrict__ src,
                           __nv_bfloat16* __restrict__ hi,
                           __nv_bfloat16* __restrict__ lo, size_t n4)
{
    size_t i = (size_t)blockIdx.x * blockDim.x + threadIdx.x;
    if (i >= n4) return;
    float4 v = ((const float4*)src)[i];
    __nv_bfloat16 h0 = __float2bfloat16(v.x);
    __nv_bfloat16 h1 = __float2bfloat16(v.y);
    __nv_bfloat16 h2 = __float2bfloat16(v.z);
    __nv_bfloat16 h3 = __float2bfloat16(v.w);
    __nv_bfloat162* hp = (__nv_bfloat162*)hi;
    __nv_bfloat162* lp = (__nv_bfloat162*)lo;
    hp[i * 2 + 0] = __nv_bfloat162(h0, h1);
    hp[i * 2 + 1] = __nv_bfloat162(h2, h3);
    lp[i * 2 + 0] = __nv_bfloat162(
        __float2bfloat16(v.x - __bfloat162float(h0)),
        __float2bfloat16(v.y - __bfloat162float(h1)));
    lp[i * 2 + 1] = __nv_bfloat162(
        __float2bfloat16(v.z - __bfloat162float(h2)),
        __float2bfloat16(v.w - __bfloat162float(h3)));
}

// ---------------------------------------------------------------------------
// W [K,N] row-major -> [N,K] K-major bf16 hi/lo (transpose + split)
// ---------------------------------------------------------------------------
__global__ void transpose_split(const float* __restrict__ W,
                                __nv_bfloat16* __restrict__ hi,
                                __nv_bfloat16* __restrict__ lo, int K, int N)
{
    __shared__ float t[32][33];
    int n0 = blockIdx.x * 32, k0 = blockIdx.y * 32;
    for (int r = threadIdx.y; r < 32; r += 8)
        t[r][threadIdx.x] = W[(size_t)(k0 + r) * N + n0 + threadIdx.x];
    __syncthreads();
    for (int r = threadIdx.y; r < 32; r += 8) {
        float v = t[threadIdx.x][r];            // = W[k0+tx][n0+r]
        __nv_bfloat16 h = __float2bfloat16(v);
        size_t o = (size_t)(n0 + r) * K + k0 + threadIdx.x;
        hi[o] = h;
        lo[o] = __float2bfloat16(v - __bfloat162float(h));
    }
}

// ---------------------------------------------------------------------------
// Window attention. Grid: (LWIN, NHEADS, B). Block: 256 threads.
// Emits hi/lo bf16 for stage 3.
// ---------------------------------------------------------------------------
__global__ __launch_bounds__(256)
void win_attn_kernel()
{
    float* smem = (float*)smem_raw;
    float* sk = smem;
    float* sv = smem + NWTOK * HDIM;

    const int l    = blockIdx.x;
    const int head = blockIdx.y;
    const int b    = blockIdx.z;
    const int wy   = l / NW_WIN;
    const int wx   = l % NW_WIN;
    const int tid  = threadIdx.x;

    const int NE4 = NWTOK * HDIM / 4;
    for (int e4 = tid; e4 < NE4; e4 += 256) {
        int j  = e4 / (HDIM / 4);
        int d4 = (e4 % (HDIM / 4)) * 4;
        int r  = j / WIN;
        int c  = j % WIN;
        int hh = wy * WIN + r;
        int ww = wx * WIN + c;
        float4 kv = make_float4(0.f, 0.f, 0.f, 0.f);
        float4 vv = kv;
        if (hh < H_IMG && ww < W_IMG) {
            size_t base = ((size_t)(b * NTOK + hh * W_IMG + ww)) * QKV_DIM
                          + (size_t)head * HDIM + d4;
            kv = *(const float4*)&g_qkv[base + C_DIM];
            vv = *(const float4*)&g_qkv[base + 2 * C_DIM];
        }
        *(float4*)&sk[j * HDIM + d4] = kv;
        *(float4*)&sv[j * HDIM + d4] = vv;
    }
    __syncthreads();

    if (tid >= NWTOK) return;
    const int r  = tid / WIN;
    const int c  = tid % WIN;
    const int hh = wy * WIN + r;
    const int ww = wx * WIN + c;
    if (hh >= H_IMG || ww >= W_IMG) return;

    const size_t qbase = ((size_t)(b * NTOK + hh * W_IMG + ww)) * QKV_DIM
                         + (size_t)head * HDIM;
    float q[HDIM];
#pragma unroll
    for (int d4 = 0; d4 < HDIM; d4 += 4) {
        float4 t = *(const float4*)&g_qkv[qbase + d4];
        q[d4 + 0] = t.x; q[d4 + 1] = t.y; q[d4 + 2] = t.z; q[d4 + 3] = t.w;
    }

    float o[HDIM];
#pragma unroll
    for (int d = 0; d < HDIM; d++) o[d] = 0.f;
    float m = -1e30f, lsum = 0.f;
    const float scale = 0.125f;

    for (int j = 0; j < NWTOK; j++) {
        const float* kj = &sk[j * HDIM];
        float s = 0.f;
#pragma unroll
        for (int d = 0; d < HDIM; d++) s += q[d] * kj[d];
        s *= scale;
        float mnew = fmaxf(m, s);
        float corr = __expf(m - mnew);
        float p    = __expf(s - mnew);
        lsum = lsum * corr + p;
        const float* vj = &sv[j * HDIM];
#pragma unroll
        for (int d = 0; d < HDIM; d++) o[d] = o[d] * corr + p * vj[d];
        m = mnew;
    }

    const float inv = 1.f / lsum;
    const size_t obase = ((size_t)(b * NTOK + hh * W_IMG + ww)) * C_DIM
                         + (size_t)head * HDIM;
#pragma unroll
    for (int d = 0; d < HDIM; d++) {
        float v = o[d] * inv;
        __nv_bfloat16 h = __float2bfloat16(v);
        g_atthi[obase + d] = h;
        g_attlo[obase + d] = __float2bfloat16(v - __bfloat162float(h));
    }
}

// ---------------------------------------------------------------------------
// Launch
// ---------------------------------------------------------------------------
extern "C" void kernel_launch(void* const* d_in, const int* in_sizes, int n_in,
                              void* d_out, int out_size)
{
    const float* x     = (const float*)d_in[0];
    const float* Wqkv  = (const float*)d_in[1];
    const float* Wproj = (const float*)d_in[2];
    const float* bproj = (const float*)d_in[3];
    float* out = (float*)d_out;

    float *qkvp;
    __nv_bfloat16 *xhi, *xlo, *wqh, *wql, *wph, *wpl, *athi, *atlo;
    cudaGetSymbolAddress((void**)&qkvp, g_qkv);
    cudaGetSymbolAddress((void**)&xhi,  g_xhi);
    cudaGetSymbolAddress((void**)&xlo,  g_xlo);
    cudaGetSymbolAddress((void**)&wqh,  g_wqkv_hi);
    cudaGetSymbolAddress((void**)&wql,  g_wqkv_lo);
    cudaGetSymbolAddress((void**)&wph,  g_wproj_hi);
    cudaGetSymbolAddress((void**)&wpl,  g_wproj_lo);
    cudaGetSymbolAddress((void**)&athi, g_atthi);
    cudaGetSymbolAddress((void**)&atlo, g_attlo);

    // convert x + weights to bf16 hi/lo
    {
        size_t n4 = (size_t)MTOT * C_DIM / 4;
        split_fp32<<<(unsigned)((n4 + 255) / 256), 256>>>(x, xhi, xlo, n4);
        transpose_split<<<dim3(QKV_DIM / 32, C_DIM / 32), dim3(32, 8)>>>(Wqkv, wqh, wql, C_DIM, QKV_DIM);
        transpose_split<<<dim3(C_DIM / 32,  C_DIM / 32), dim3(32, 8)>>>(Wproj, wph, wpl, C_DIM, C_DIM);
    }

    cudaFuncSetAttribute(wmma_gemm, cudaFuncAttributeMaxDynamicSharedMemorySize, GEMM_SMEM);

    // Stage 1: qkv = x @ Wqkv   [51200,768] x [768,2304]
    wmma_gemm<<<dim3(QKV_DIM / GBN, MTOT / GBM), 256, GEMM_SMEM>>>(
        xhi, xlo, wqh, wql, nullptr, qkvp, QKV_DIM);

    // Stage 2: windowed attention
    {
        const int smem_bytes = 2 * NWTOK * HDIM * (int)sizeof(float);
        cudaFuncSetAttribute(win_attn_kernel,
                             cudaFuncAttributeMaxDynamicSharedMemorySize, smem_bytes);
        dim3 grid(LWIN, NHEADS, B_SZ);
        win_attn_kernel<<<grid, 256, smem_bytes>>>();
    }

    // Stage 3: out = att @ Wproj + bproj   [51200,768] x [768,768]
    wmma_gemm<<<dim3(C_DIM / GBN, MTOT / GBM), 256, GEMM_SMEM>>>(
        athi, atlo, wph, wpl, bproj, out, C_DIM);
}

// round 5
// speedup vs baseline: 2.8182x; 1.6981x over previous
#include <cuda_runtime.h>
#include <cuda_bf16.h>
#include <math.h>
#include <stdint.h>

// ---------------------------------------------------------------------------
// WindowedAttention on GB300 (sm_103a chip; ptxas target is base sm_103 so
// tcgen05 unavailable — everything runs on warp-level mma.sync bf16).
// Stages 1 & 3: bf16 hi/lo-split (3-term) HMMA GEMM, fp32 accumulate.
// Stage 2 (R4): fused MMA attention, two-pass exact softmax, 13 warps/CTA.
// ---------------------------------------------------------------------------

#define C_DIM    768
#define QKV_DIM  2304
#define B_SZ     8
#define H_IMG    80
#define W_IMG    80
#define NTOK     (H_IMG * W_IMG)     // 6400
#define WIN      14
#define NW_WIN   6
#define LWIN     36
#define NWTOK    (WIN * WIN)         // 196
#define NHEADS   12
#define HDIM     64
#define MTOT     (B_SZ * NTOK)       // 51200

// ---------------- scratch (__device__ globals: allocation-free rule) -------
__device__ float          g_qkv[(size_t)MTOT * QKV_DIM];        // fp32 qkv
__device__ __nv_bfloat16  g_xhi[(size_t)MTOT * C_DIM];
__device__ __nv_bfloat16  g_xlo[(size_t)MTOT * C_DIM];
__device__ __nv_bfloat16  g_wqkv_hi[(size_t)QKV_DIM * C_DIM];   // [N,K] K-major
__device__ __nv_bfloat16  g_wqkv_lo[(size_t)QKV_DIM * C_DIM];
__device__ __nv_bfloat16  g_wproj_hi[(size_t)C_DIM * C_DIM];    // [N,K] K-major
__device__ __nv_bfloat16  g_wproj_lo[(size_t)C_DIM * C_DIM];
__device__ __nv_bfloat16  g_atthi[(size_t)MTOT * C_DIM];
__device__ __nv_bfloat16  g_attlo[(size_t)MTOT * C_DIM];

extern __shared__ char smem_raw[];

// ---------------------------- PTX helpers ----------------------------------
__device__ __forceinline__ uint32_t smem_u32(const void* p) {
    uint32_t a;
    asm("{ .reg .u64 t; cvta.to.shared.u64 t, %1; cvt.u32.u64 %0, t; }"
        : "=r"(a) : "l"(p));
    return a;
}
__device__ __forceinline__ void cp16(uint32_t saddr, const void* g) {
    asm volatile("cp.async.cg.shared.global [%0], [%1], 16;" :: "r"(saddr), "l"(g));
}
__device__ __forceinline__ void cp_commit() { asm volatile("cp.async.commit_group;" ::: "memory"); }
template <int N> __device__ __forceinline__ void cp_wait() {
    asm volatile("cp.async.wait_group %0;" :: "n"(N) : "memory");
}
__device__ __forceinline__ void ldm_x4(uint32_t* r, uint32_t addr) {
    asm volatile("ldmatrix.sync.aligned.m8n8.x4.shared.b16 {%0,%1,%2,%3}, [%4];"
        : "=r"(r[0]), "=r"(r[1]), "=r"(r[2]), "=r"(r[3]) : "r"(addr));
}
__device__ __forceinline__ void mma16816(float* d, const uint32_t* a, const uint32_t* b) {
    asm volatile(
        "mma.sync.aligned.m16n8k16.row.col.f32.bf16.bf16.f32 "
        "{%0,%1,%2,%3}, {%4,%5,%6,%7}, {%8,%9}, {%0,%1,%2,%3};"
        : "+f"(d[0]), "+f"(d[1]), "+f"(d[2]), "+f"(d[3])
        : "r"(a[0]), "r"(a[1]), "r"(a[2]), "r"(a[3]), "r"(b[0]), "r"(b[1]));
}
// pack two fp32 -> bf16x2 register (lo = first, hi = second)
__device__ __forceinline__ uint32_t pack_bf16(float lo, float hi) {
    uint32_t r;
    asm("cvt.rn.bf16x2.f32 %0, %1, %2;" : "=r"(r) : "f"(hi), "f"(lo));
    return r;
}

// ---------------------------------------------------------------------------
// Warp-MMA GEMM: C[M,N] = (Ahi+Alo)[M,768] @ (Bhi+Blo)[N,768]^T (+ bias)
// ---------------------------------------------------------------------------
#define GBM 128
#define GBN 128
#define GBK 32
#define GNCH (768 / GBK)         // 24
#define ROWB 80
#define OFF_AHI 0
#define OFF_ALO 10240
#define OFF_BHI 20480
#define OFF_BLO 30720
#define STG_SZ  40960
#define GEMM_SMEM (2 * STG_SZ)   // 81920

__device__ __forceinline__ void gemm_load_chunk(
    uint32_t buf,
    const __nv_bfloat16* __restrict__ Ahi, const __nv_bfloat16* __restrict__ Alo,
    const __nv_bfloat16* __restrict__ Bhi, const __nv_bfloat16* __restrict__ Blo,
    int rowBase, int colBase, int k0, int tid)
{
#pragma unroll
    for (int it = 0; it < 2; it++) {
        int t = tid + it * 256;
        int r = t >> 2;
        int c = t & 3;
        uint32_t soff = (uint32_t)(r * ROWB + c * 16);
        size_t ga = (size_t)(rowBase + r) * 768 + k0 + c * 8;
        size_t gb = (size_t)(colBase + r) * 768 + k0 + c * 8;
        cp16(buf + OFF_AHI + soff, Ahi + ga);
        cp16(buf + OFF_ALO + soff, Alo + ga);
        cp16(buf + OFF_BHI + soff, Bhi + gb);
        cp16(buf + OFF_BLO + soff, Blo + gb);
    }
    cp_commit();
}

__global__ void __launch_bounds__(256)
wmma_gemm(const __nv_bfloat16* __restrict__ Ahi, const __nv_bfloat16* __restrict__ Alo,
          const __nv_bfloat16* __restrict__ Bhi, const __nv_bfloat16* __restrict__ Blo,
          const float* __restrict__ bias, float* __restrict__ C, int N)
{
    const uint32_t sb = smem_u32(smem_raw);
    const int tid   = threadIdx.x;
    const int lane  = tid & 31;
    const int wid   = tid >> 5;
    const int warpM = wid >> 2;
    const int warpN = wid & 3;
    const int rowBase = blockIdx.y * GBM;
    const int colBase = blockIdx.x * GBN;

    float acc[4][4][4];
#pragma unroll
    for (int i = 0; i < 4; i++)
#pragma unroll
        for (int j = 0; j < 4; j++)
#pragma unroll
            for (int e = 0; e < 4; e++) acc[i][j][e] = 0.f;

    const uint32_t a_lane = (uint32_t)((warpM * 64 + (lane & 15)) * ROWB + (lane >> 4) * 16);
    const uint32_t b_lane = (uint32_t)((warpN * 32 + ((lane & 7) | ((lane >> 4) << 3))) * ROWB
                                       + ((lane >> 3) & 1) * 16);

    gemm_load_chunk(sb,          Ahi, Alo, Bhi, Blo, rowBase, colBase, 0,   tid);
    gemm_load_chunk(sb + STG_SZ, Ahi, Alo, Bhi, Blo, rowBase, colBase, GBK, tid);

    for (int ch = 0; ch < GNCH; ch++) {
        if (ch == GNCH - 1) cp_wait<0>(); else cp_wait<1>();
        __syncthreads();
        const uint32_t buf = sb + (uint32_t)(ch & 1) * STG_SZ;

#pragma unroll
        for (int k16 = 0; k16 < 2; k16++) {
            const uint32_t kb = (uint32_t)(k16 * 32);
            uint32_t ah[4][4], al[4][4];
#pragma unroll
            for (int mt = 0; mt < 4; mt++) {
                uint32_t ao = buf + a_lane + kb + (uint32_t)(mt * 16 * ROWB);
                ldm_x4(ah[mt], ao + OFF_AHI);
                ldm_x4(al[mt], ao + OFF_ALO);
            }
            uint32_t bh[2][4], bl[2][4];
#pragma unroll
            for (int half = 0; half < 2; half++) {
                uint32_t bo = buf + b_lane + kb + (uint32_t)(half * 16 * ROWB);
                ldm_x4(bh[half], bo + OFF_BHI);
                ldm_x4(bl[half], bo + OFF_BLO);
            }
#pragma unroll
            for (int mt = 0; mt < 4; mt++)
#pragma unroll
                for (int nt = 0; nt < 4; nt++) {
                    const uint32_t* bhf = &bh[nt >> 1][(nt & 1) * 2];
                    const uint32_t* blf = &bl[nt >> 1][(nt & 1) * 2];
                    mma16816(acc[mt][nt], ah[mt], bhf);
                    mma16816(acc[mt][nt], ah[mt], blf);
                    mma16816(acc[mt][nt], al[mt], bhf);
                }
        }
        __syncthreads();
        if (ch + 2 < GNCH)
            gemm_load_chunk(buf, Ahi, Alo, Bhi, Blo, rowBase, colBase,
                            (ch + 2) * GBK, tid);
    }

#pragma unroll
    for (int mt = 0; mt < 4; mt++) {
        const int row0 = rowBase + warpM * 64 + mt * 16 + (lane >> 2);
#pragma unroll
        for (int nt = 0; nt < 4; nt++) {
            const int col = colBase + warpN * 32 + nt * 8 + (lane & 3) * 2;
            float b0 = 0.f, b1 = 0.f;
            if (bias != nullptr) { b0 = bias[col]; b1 = bias[col + 1]; }
            float2 v0 = make_float2(acc[mt][nt][0] + b0, acc[mt][nt][1] + b1);
            float2 v1 = make_float2(acc[mt][nt][2] + b0, acc[mt][nt][3] + b1);
            *(float2*)&C[(size_t)row0 * N + col]       = v0;
            *(float2*)&C[(size_t)(row0 + 8) * N + col] = v1;
        }
    }
}

// ---------------------------------------------------------------------------
// fp32 -> bf16 hi/lo elementwise split (for x)
// ---------------------------------------------------------------------------
__global__ void split_fp32(const float* __restrict__ src,
                           __nv_bfloat16* __restrict__ hi,
                           __nv_bfloat16* __restrict__ lo, size_t n4)
{
    size_t i = (size_t)blockIdx.x * blockDim.x + threadIdx.x;
    if (i >= n4) return;
    float4 v = ((const float4*)src)[i];
    __nv_bfloat16 h0 = __float2bfloat16(v.x);
    __nv_bfloat16 h1 = __float2bfloat16(v.y);
    __nv_bfloat16 h2 = __float2bfloat16(v.z);
    __nv_bfloat16 h3 = __float2bfloat16(v.w);
    __nv_bfloat162* hp = (__nv_bfloat162*)hi;
    __nv_bfloat162* lp = (__nv_bfloat162*)lo;
    hp[i * 2 + 0] = __nv_bfloat162(h0, h1);
    hp[i * 2 + 1] = __nv_bfloat162(h2, h3);
    lp[i * 2 + 0] = __nv_bfloat162(
        __float2bfloat16(v.x - __bfloat162float(h0)),
        __float2bfloat16(v.y - __bfloat162float(h1)));
    lp[i * 2 + 1] = __nv_bfloat162(
        __float2bfloat16(v.z - __bfloat162float(h2)),
        __float2bfloat16(v.w - __bfloat162float(h3)));
}

// ---------------------------------------------------------------------------
// W [K,N] row-major -> [N,K] K-major bf16 hi/lo (transpose + split)
// ---------------------------------------------------------------------------
__global__ void transpose_split(const float* __restrict__ W,
                                __nv_bfloat16* __restrict__ hi,
                                __nv_bfloat16* __restrict__ lo, int K, int N)
{
    __shared__ float t[32][33];
    int n0 = blockIdx.x * 32, k0 = blockIdx.y * 32;
    for (int r = threadIdx.y; r < 32; r += 8)
        t[r][threadIdx.x] = W[(size_t)(k0 + r) * N + n0 + threadIdx.x];
    __syncthreads();
    for (int r = threadIdx.y; r < 32; r += 8) {
        float v = t[threadIdx.x][r];
        __nv_bfloat16 h = __float2bfloat16(v);
        size_t o = (size_t)(n0 + r) * K + k0 + threadIdx.x;
        hi[o] = h;
        lo[o] = __float2bfloat16(v - __bfloat162float(h));
    }
}

// ---------------------------------------------------------------------------
// Fused MMA attention. Grid (LWIN, NHEADS, B), block 416 (13 warps).
// Warp w owns query rows 16w..16w+15 (208 padded rows cover 196).
// smem: Q,K as [row 208][64] bf16 hi/lo (row stride 144B);
//       V^T as [d 64][keys 208] bf16 hi/lo (row stride 432B).
// Pass 1: S = Qs @ K^T (3-term MMA) -> row max.  Pass 2: recompute S,
// p = exp(s-m) (cols >=196 masked), O += P@V (3-term), row-sum; O /= sum.
// ---------------------------------------------------------------------------
#define MPAD   208
#define QK_ROWB 144
#define VT_ROWB 432
#define SQ_HI  0
#define SQ_LO  29952
#define SK_HI  59904
#define SK_LO  89856
#define SV_HI  119808
#define SV_LO  147456
#define ATT_SMEM 175104
#define ATT_THREADS 416

__global__ void __launch_bounds__(ATT_THREADS, 1)
win_attn_mma()
{
    const uint32_t sb = smem_u32(smem_raw);
    const int l    = blockIdx.x;
    const int head = blockIdx.y;
    const int b    = blockIdx.z;
    const int wy   = l / NW_WIN;
    const int wx   = l % NW_WIN;
    const int tid  = threadIdx.x;
    const int lane = tid & 31;
    const int w    = tid >> 5;       // 0..12

    // ---- load Q (scaled by 0.125) and K into smem as bf16 hi/lo ----
#pragma unroll
    for (int it = 0; it < 8; it++) {
        int idx = tid + it * ATT_THREADS;      // 0..3327
        int row = idx >> 4;                    // 0..207
        int d4  = (idx & 15) * 4;
        int rr = row / WIN, cc = row % WIN;
        int hh = wy * WIN + rr, ww = wx * WIN + cc;
        bool valid = (row < NWTOK) && (hh < H_IMG) && (ww < W_IMG);
        float4 qv = make_float4(0.f, 0.f, 0.f, 0.f);
        float4 kv = qv;
        if (valid) {
            size_t base = ((size_t)(b * NTOK + hh * W_IMG + ww)) * QKV_DIM
                          + (size_t)head * HDIM + d4;
            qv = *(const float4*)&g_qkv[base];
            kv = *(const float4*)&g_qkv[base + C_DIM];
            qv.x *= 0.125f; qv.y *= 0.125f; qv.z *= 0.125f; qv.w *= 0.125f;
        }
        uint32_t off = (uint32_t)(row * QK_ROWB + d4 * 2);
        // Q
        {
            __nv_bfloat16 h0 = __float2bfloat16(qv.x), h1 = __float2bfloat16(qv.y);
            __nv_bfloat16 h2 = __float2bfloat16(qv.z), h3 = __float2bfloat16(qv.w);
            *(__nv_bfloat162*)(smem_raw + SQ_HI + off)     = __nv_bfloat162(h0, h1);
            *(__nv_bfloat162*)(smem_raw + SQ_HI + off + 4) = __nv_bfloat162(h2, h3);
            *(__nv_bfloat162*)(smem_raw + SQ_LO + off)     = __nv_bfloat162(
                __float2bfloat16(qv.x - __bfloat162float(h0)),
                __float2bfloat16(qv.y - __bfloat162float(h1)));
            *(__nv_bfloat162*)(smem_raw + SQ_LO + off + 4) = __nv_bfloat162(
                __float2bfloat16(qv.z - __bfloat162float(h2)),
                __float2bfloat16(qv.w - __bfloat162float(h3)));
        }
        // K
        {
            __nv_bfloat16 h0 = __float2bfloat16(kv.x), h1 = __float2bfloat16(kv.y);
            __nv_bfloat16 h2 = __float2bfloat16(kv.z), h3 = __float2bfloat16(kv.w);
            *(__nv_bfloat162*)(smem_raw + SK_HI + off)     = __nv_bfloat162(h0, h1);
            *(__nv_bfloat162*)(smem_raw + SK_HI + off + 4) = __nv_bfloat162(h2, h3);
            *(__nv_bfloat162*)(smem_raw + SK_LO + off)     = __nv_bfloat162(
                __float2bfloat16(kv.x - __bfloat162float(h0)),
                __float2bfloat16(kv.y - __bfloat162float(h1)));
            *(__nv_bfloat162*)(smem_raw + SK_LO + off + 4) = __nv_bfloat162(
                __float2bfloat16(kv.z - __bfloat162float(h2)),
                __float2bfloat16(kv.w - __bfloat162float(h3)));
        }
    }
    // ---- load V transposed: V^T[d][key] ----
#pragma unroll
    for (int it = 0; it < 8; it++) {
        int idx = tid + it * ATT_THREADS;
        int j  = idx >> 4;                     // key 0..207
        int d4 = (idx & 15) * 4;
        int rr = j / WIN, cc = j % WIN;
        int hh = wy * WIN + rr, ww = wx * WIN + cc;
        bool valid = (j < NWTOK) && (hh < H_IMG) && (ww < W_IMG);
        float4 vv = make_float4(0.f, 0.f, 0.f, 0.f);
        if (valid) {
            size_t base = ((size_t)(b * NTOK + hh * W_IMG + ww)) * QKV_DIM
                          + (size_t)head * HDIM + d4 + 2 * C_DIM;
            vv = *(const float4*)&g_qkv[base];
        }
        float ve[4] = {vv.x, vv.y, vv.z, vv.w};
#pragma unroll
        for (int e = 0; e < 4; e++) {
            __nv_bfloat16 h = __float2bfloat16(ve[e]);
            uint32_t off = (uint32_t)((d4 + e) * VT_ROWB + j * 2);
            *(__nv_bfloat16*)(smem_raw + SV_HI + off) = h;
            *(__nv_bfloat16*)(smem_raw + SV_LO + off) =
                __float2bfloat16(ve[e] - __bfloat162float(h));
        }
    }
    __syncthreads();

    // ---- per-warp fragment addresses ----
    const uint32_t a_lane  = sb + (uint32_t)((w * 16 + (lane & 15)) * QK_ROWB + (lane >> 4) * 16);
    const uint32_t kb_lane = sb + SK_HI
        + (uint32_t)((((lane & 7) | ((lane >> 4) << 3))) * QK_ROWB + ((lane >> 3) & 1) * 16);
    const uint32_t vb_lane = sb + SV_HI
        + (uint32_t)((((lane & 7) | ((lane >> 4) << 3))) * VT_ROWB + ((lane >> 3) & 1) * 16);

    // ---- Q fragments (persistent) ----
    uint32_t qah[4][4], qal[4][4];
#pragma unroll
    for (int kt = 0; kt < 4; kt++) {
        ldm_x4(qah[kt], a_lane + SQ_HI + kt * 32);
        ldm_x4(qal[kt], a_lane + SQ_LO + kt * 32);
    }

    const int cq = 2 * (lane & 3);   // col offset within n8 tile

    // ---- pass 1: row max ----
    float m0 = -1e30f, m1 = -1e30f;
    for (int t = 0; t < 13; t++) {
        uint32_t kbh[4][4], kbl[4][4];
#pragma unroll
        for (int kt = 0; kt < 4; kt++) {
            uint32_t addr = kb_lane + (uint32_t)(t * 16 * QK_ROWB + kt * 32);
            ldm_x4(kbh[kt], addr);
            ldm_x4(kbl[kt], addr + (SK_LO - SK_HI));
        }
        float s0[4] = {0.f, 0.f, 0.f, 0.f}, s1[4] = {0.f, 0.f, 0.f, 0.f};
#pragma unroll
        for (int kt = 0; kt < 4; kt++) {
            mma16816(s0, qah[kt], &kbh[kt][0]);
            mma16816(s0, qah[kt], &kbl[kt][0]);
            mma16816(s0, qal[kt], &kbh[kt][0]);
            mma16816(s1, qah[kt], &kbh[kt][2]);
            mma16816(s1, qah[kt], &kbl[kt][2]);
            mma16816(s1, qal[kt], &kbh[kt][2]);
        }
        int j0 = t * 16 + cq;        // ntile 2t cols
        int j1 = j0 + 8;             // ntile 2t+1 cols
        if (j0     < NWTOK) { m0 = fmaxf(m0, s0[0]); m1 = fmaxf(m1, s0[2]); }
        if (j0 + 1 < NWTOK) { m0 = fmaxf(m0, s0[1]); m1 = fmaxf(m1, s0[3]); }
        if (j1     < NWTOK) { m0 = fmaxf(m0, s1[0]); m1 = fmaxf(m1, s1[2]); }
        if (j1 + 1 < NWTOK) { m0 = fmaxf(m0, s1[1]); m1 = fmaxf(m1, s1[3]); }
    }
#pragma unroll
    for (int off = 1; off <= 2; off <<= 1) {
        m0 = fmaxf(m0, __shfl_xor_sync(0xffffffffu, m0, off));
        m1 = fmaxf(m1, __shfl_xor_sync(0xffffffffu, m1, off));
    }

    // ---- pass 2: recompute S, P = exp(s-m), O += P@V, row sums ----
    float o[8][4];
#pragma unroll
    for (int i = 0; i < 8; i++)
#pragma unroll
        for (int e = 0; e < 4; e++) o[i][e] = 0.f;
    float sum0 = 0.f, sum1 = 0.f;

    for (int t = 0; t < 13; t++) {
        uint32_t kbh[4][4], kbl[4][4];
#pragma unroll
        for (int kt = 0; kt < 4; kt++) {
            uint32_t addr = kb_lane + (uint32_t)(t * 16 * QK_ROWB + kt * 32);
            ldm_x4(kbh[kt], addr);
            ldm_x4(kbl[kt], addr + (SK_LO - SK_HI));
        }
        float s0[4] = {0.f, 0.f, 0.f, 0.f}, s1[4] = {0.f, 0.f, 0.f, 0.f};
#pragma unroll
        for (int kt = 0; kt < 4; kt++) {
            mma16816(s0, qah[kt], &kbh[kt][0]);
            mma16816(s0, qah[kt], &kbl[kt][0]);
            mma16816(s0, qal[kt], &kbh[kt][0]);
            mma16816(s1, qah[kt], &kbh[kt][2]);
            mma16816(s1, qah[kt], &kbl[kt][2]);
            mma16816(s1, qal[kt], &kbh[kt][2]);
        }
        int j0 = t * 16 + cq;
        int j1 = j0 + 8;
        float p0 = (j0     < NWTOK) ? __expf(s0[0] - m0) : 0.f;
        float p1 = (j0 + 1 < NWTOK) ? __expf(s0[1] - m0) : 0.f;
        float p2 = (j0     < NWTOK) ? __expf(s0[2] - m1) : 0.f;
        float p3 = (j0 + 1 < NWTOK) ? __expf(s0[3] - m1) : 0.f;
        float u0 = (j1     < NWTOK) ? __expf(s1[0] - m0) : 0.f;
        float u1 = (j1 + 1 < NWTOK) ? __expf(s1[1] - m0) : 0.f;
        float u2 = (j1     < NWTOK) ? __expf(s1[2] - m1) : 0.f;
        float u3 = (j1 + 1 < NWTOK) ? __expf(s1[3] - m1) : 0.f;
        sum0 += p0 + p1 + u0 + u1;
        sum1 += p2 + p3 + u2 + u3;

        // pack to A fragments (hi) and residual (lo)
        float h0 = __bfloat162float(__float2bfloat16(p0));
        float h1 = __bfloat162float(__float2bfloat16(p1));
        float h2 = __bfloat162float(__float2bfloat16(p2));
        float h3 = __bfloat162float(__float2bfloat16(p3));
        float g0 = __bfloat162float(__float2bfloat16(u0));
        float g1 = __bfloat162float(__float2bfloat16(u1));
        float g2 = __bfloat162float(__float2bfloat16(u2));
        float g3 = __bfloat162float(__float2bfloat16(u3));
        uint32_t pah[4], pal[4];
        pah[0] = pack_bf16(p0, p1);   pah[1] = pack_bf16(p2, p3);
        pah[2] = pack_bf16(u0, u1);   pah[3] = pack_bf16(u2, u3);
        pal[0] = pack_bf16(p0 - h0, p1 - h1);
        pal[1] = pack_bf16(p2 - h2, p3 - h3);
        pal[2] = pack_bf16(u0 - g0, u1 - g1);
        pal[3] = pack_bf16(u2 - g2, u3 - g3);

#pragma unroll
        for (int dg = 0; dg < 4; dg++) {
            uint32_t vbh[4], vbl[4];
            uint32_t addr = vb_lane + (uint32_t)(dg * 16 * VT_ROWB + t * 32);
            ldm_x4(vbh, addr);
            ldm_x4(vbl, addr + (SV_LO - SV_HI));
            mma16816(o[dg * 2 + 0], pah, &vbh[0]);
            mma16816(o[dg * 2 + 0], pah, &vbl[0]);
            mma16816(o[dg * 2 + 0], pal, &vbh[0]);
            mma16816(o[dg * 2 + 1], pah, &vbh[2]);
            mma16816(o[dg * 2 + 1], pah, &vbl[2]);
            mma16816(o[dg * 2 + 1], pal, &vbh[2]);
        }
    }
#pragma unroll
    for (int off = 1; off <= 2; off <<= 1) {
        sum0 += __shfl_xor_sync(0xffffffffu, sum0, off);
        sum1 += __shfl_xor_sync(0xffffffffu, sum1, off);
    }
    const float inv0 = 1.f / sum0;
    const float inv1 = 1.f / sum1;

    // ---- epilogue: O/sum -> g_atthi/lo (hi/lo bf16 split) ----
    const int r0 = w * 16 + (lane >> 2);
#pragma unroll
    for (int half = 0; half < 2; half++) {
        const int row = r0 + half * 8;
        if (row >= NWTOK) continue;
        const int rr = row / WIN, cc = row % WIN;
        const int hh = wy * WIN + rr, ww = wx * WIN + cc;
        if (hh >= H_IMG || ww >= W_IMG) continue;
        const float inv = half ? inv1 : inv0;
        const size_t obase = ((size_t)(b * NTOK + hh * W_IMG + ww)) * C_DIM
                             + (size_t)head * HDIM;
#pragma unroll
        for (int dt = 0; dt < 8; dt++) {
            const int col = dt * 8 + cq;
            float v0 = o[dt][half * 2 + 0] * inv;
            float v1 = o[dt][half * 2 + 1] * inv;
            __nv_bfloat16 h0 = __float2bfloat16(v0);
            __nv_bfloat16 h1 = __float2bfloat16(v1);
            *(__nv_bfloat162*)&g_atthi[obase + col] = __nv_bfloat162(h0, h1);
            *(__nv_bfloat162*)&g_attlo[obase + col] = __nv_bfloat162(
                __float2bfloat16(v0 - __bfloat162float(h0)),
                __float2bfloat16(v1 - __bfloat162float(h1)));
        }
    }
}

// ---------------------------------------------------------------------------
// Launch
// ---------------------------------------------------------------------------
extern "C" void kernel_launch(void* const* d_in, const int* in_sizes, int n_in,
                              void* d_out, int out_size)
{
    const float* x     = (const float*)d_in[0];
    const float* Wqkv  = (const float*)d_in[1];
    const float* Wproj = (const float*)d_in[2];
    const float* bproj = (const float*)d_in[3];
    float* out = (float*)d_out;

    float *qkvp;
    __nv_bfloat16 *xhi, *xlo, *wqh, *wql, *wph, *wpl, *athi, *atlo;
    cudaGetSymbolAddress((void**)&qkvp, g_qkv);
    cudaGetSymbolAddress((void**)&xhi,  g_xhi);
    cudaGetSymbolAddress((void**)&xlo,  g_xlo);
    cudaGetSymbolAddress((void**)&wqh,  g_wqkv_hi);
    cudaGetSymbolAddress((void**)&wql,  g_wqkv_lo);
    cudaGetSymbolAddress((void**)&wph,  g_wproj_hi);
    cudaGetSymbolAddress((void**)&wpl,  g_wproj_lo);
    cudaGetSymbolAddress((void**)&athi, g_atthi);
    cudaGetSymbolAddress((void**)&atlo, g_attlo);

    // convert x + weights to bf16 hi/lo
    {
        size_t n4 = (size_t)MTOT * C_DIM / 4;
        split_fp32<<<(unsigned)((n4 + 255) / 256), 256>>>(x, xhi, xlo, n4);
        transpose_split<<<dim3(QKV_DIM / 32, C_DIM / 32), dim3(32, 8)>>>(Wqkv, wqh, wql, C_DIM, QKV_DIM);
        transpose_split<<<dim3(C_DIM / 32,  C_DIM / 32), dim3(32, 8)>>>(Wproj, wph, wpl, C_DIM, C_DIM);
    }

    cudaFuncSetAttribute(wmma_gemm, cudaFuncAttributeMaxDynamicSharedMemorySize, GEMM_SMEM);
    cudaFuncSetAttribute(win_attn_mma, cudaFuncAttributeMaxDynamicSharedMemorySize, ATT_SMEM);

    // Stage 1: qkv = x @ Wqkv
    wmma_gemm<<<dim3(QKV_DIM / GBN, MTOT / GBM), 256, GEMM_SMEM>>>(
        xhi, xlo, wqh, wql, nullptr, qkvp, QKV_DIM);

    // Stage 2: fused MMA attention
    win_attn_mma<<<dim3(LWIN, NHEADS, B_SZ), ATT_THREADS, ATT_SMEM>>>();

    // Stage 3: out = att @ Wproj + bproj
    wmma_gemm<<<dim3(C_DIM / GBN, MTOT / GBM), 256, GEMM_SMEM>>>(
        athi, atlo, wph, wpl, bproj, out, C_DIM);
}

// round 7
// speedup vs baseline: 3.6061x; 1.2796x over previous
#include <cuda_runtime.h>
#include <cuda_bf16.h>
#include <cuda_fp16.h>
#include <math.h>
#include <stdint.h>

// ---------------------------------------------------------------------------
// WindowedAttention on GB300 (sm_103a chip; ptxas target is base sm_103 so
// tcgen05 unavailable — warp-level mma.sync tensor cores).
// R6: stages 1 & 3 use fp16 2-term split ((A_hi+A_lo) @ B_hi, fp32 accum),
//     3-stage cp.async pipeline. Attention stays bf16 3-term (R5 design).
// ---------------------------------------------------------------------------

#define C_DIM    768
#define QKV_DIM  2304
#define B_SZ     8
#define H_IMG    80
#define W_IMG    80
#define NTOK     (H_IMG * W_IMG)     // 6400
#define WIN      14
#define NW_WIN   6
#define LWIN     36
#define NWTOK    (WIN * WIN)         // 196
#define NHEADS   12
#define HDIM     64
#define MTOT     (B_SZ * NTOK)       // 51200

// ---------------- scratch (__device__ globals: allocation-free rule) -------
__device__ float   g_qkv[(size_t)MTOT * QKV_DIM];      // fp32 qkv
__device__ __half  g_xhi[(size_t)MTOT * C_DIM];
__device__ __half  g_xlo[(size_t)MTOT * C_DIM];
__device__ __half  g_wqkv_hi[(size_t)QKV_DIM * C_DIM]; // [N,K] K-major
__device__ __half  g_wproj_hi[(size_t)C_DIM * C_DIM];  // [N,K] K-major
__device__ __half  g_atthi[(size_t)MTOT * C_DIM];
__device__ __half  g_attlo[(size_t)MTOT * C_DIM];

extern __shared__ char smem_raw[];

// ---------------------------- PTX helpers ----------------------------------
__device__ __forceinline__ uint32_t smem_u32(const void* p) {
    uint32_t a;
    asm("{ .reg .u64 t; cvta.to.shared.u64 t, %1; cvt.u32.u64 %0, t; }"
        : "=r"(a) : "l"(p));
    return a;
}
__device__ __forceinline__ void cp16(uint32_t saddr, const void* g) {
    asm volatile("cp.async.cg.shared.global [%0], [%1], 16;" :: "r"(saddr), "l"(g));
}
__device__ __forceinline__ void cp_commit() { asm volatile("cp.async.commit_group;" ::: "memory"); }
template <int N> __device__ __forceinline__ void cp_wait() {
    asm volatile("cp.async.wait_group %0;" :: "n"(N) : "memory");
}
__device__ __forceinline__ void ldm_x4(uint32_t* r, uint32_t addr) {
    asm volatile("ldmatrix.sync.aligned.m8n8.x4.shared.b16 {%0,%1,%2,%3}, [%4];"
        : "=r"(r[0]), "=r"(r[1]), "=r"(r[2]), "=r"(r[3]) : "r"(addr));
}
// bf16 MMA (attention)
__device__ __forceinline__ void mma16816(float* d, const uint32_t* a, const uint32_t* b) {
    asm volatile(
        "mma.sync.aligned.m16n8k16.row.col.f32.bf16.bf16.f32 "
        "{%0,%1,%2,%3}, {%4,%5,%6,%7}, {%8,%9}, {%0,%1,%2,%3};"
        : "+f"(d[0]), "+f"(d[1]), "+f"(d[2]), "+f"(d[3])
        : "r"(a[0]), "r"(a[1]), "r"(a[2]), "r"(a[3]), "r"(b[0]), "r"(b[1]));
}
// fp16 MMA (GEMMs)
__device__ __forceinline__ void mma16816h(float* d, const uint32_t* a, const uint32_t* b) {
    asm volatile(
        "mma.sync.aligned.m16n8k16.row.col.f32.f16.f16.f32 "
        "{%0,%1,%2,%3}, {%4,%5,%6,%7}, {%8,%9}, {%0,%1,%2,%3};"
        : "+f"(d[0]), "+f"(d[1]), "+f"(d[2]), "+f"(d[3])
        : "r"(a[0]), "r"(a[1]), "r"(a[2]), "r"(a[3]), "r"(b[0]), "r"(b[1]));
}
__device__ __forceinline__ uint32_t pack_bf16(float lo, float hi) {
    uint32_t r;
    asm("cvt.rn.bf16x2.f32 %0, %1, %2;" : "=r"(r) : "f"(hi), "f"(lo));
    return r;
}

// ---------------------------------------------------------------------------
// Warp-MMA GEMM: C[M,N] = (Ahi+Alo)[M,768] @ Bhi[N,768]^T (+ bias), fp16.
// BM=BN=128, BK=32, 8 warps (2x4), warp tile 64x32, 3-stage cp.async.
// smem rows padded to 40 halves (80 B) -> conflict-free ldmatrix.
// ---------------------------------------------------------------------------
#define GBM 128
#define GBN 128
#define GBK 32
#define GNCH (768 / GBK)         // 24
#define ROWB 80
#define OFF_AHI 0
#define OFF_ALO 10240
#define OFF_BHI 20480
#define STG_SZ  30720
#define GEMM_SMEM (3 * STG_SZ)   // 92160

__device__ __forceinline__ void gemm_load_chunk(
    uint32_t buf,
    const __half* __restrict__ Ahi, const __half* __restrict__ Alo,
    const __half* __restrict__ Bhi,
    int rowBase, int colBase, int k0, int tid)
{
#pragma unroll
    for (int it = 0; it < 2; it++) {
        int t = tid + it * 256;           // 0..511
        int r = t >> 2;                   // row 0..127
        int c = t & 3;                    // 16B unit 0..3
        uint32_t soff = (uint32_t)(r * ROWB + c * 16);
        size_t ga = (size_t)(rowBase + r) * 768 + k0 + c * 8;
        size_t gb = (size_t)(colBase + r) * 768 + k0 + c * 8;
        cp16(buf + OFF_AHI + soff, Ahi + ga);
        cp16(buf + OFF_ALO + soff, Alo + ga);
        cp16(buf + OFF_BHI + soff, Bhi + gb);
    }
    cp_commit();
}

__global__ void __launch_bounds__(256)
wmma_gemm(const __half* __restrict__ Ahi, const __half* __restrict__ Alo,
          const __half* __restrict__ Bhi,
          const float* __restrict__ bias, float* __restrict__ C, int N)
{
    const uint32_t sb = smem_u32(smem_raw);
    const int tid   = threadIdx.x;
    const int lane  = tid & 31;
    const int wid   = tid >> 5;
    const int warpM = wid >> 2;
    const int warpN = wid & 3;
    const int rowBase = blockIdx.y * GBM;
    const int colBase = blockIdx.x * GBN;

    float acc[4][4][4];
#pragma unroll
    for (int i = 0; i < 4; i++)
#pragma unroll
        for (int j = 0; j < 4; j++)
#pragma unroll
            for (int e = 0; e < 4; e++) acc[i][j][e] = 0.f;

    const uint32_t a_lane = (uint32_t)((warpM * 64 + (lane & 15)) * ROWB + (lane >> 4) * 16);
    const uint32_t b_lane = (uint32_t)((warpN * 32 + ((lane & 7) | ((lane >> 4) << 3))) * ROWB
                                       + ((lane >> 3) & 1) * 16);

    gemm_load_chunk(sb,          Ahi, Alo, Bhi, rowBase, colBase, 0,   tid);
    gemm_load_chunk(sb + STG_SZ, Ahi, Alo, Bhi, rowBase, colBase, GBK, tid);

    for (int ch = 0; ch < GNCH; ch++) {
        // issue the ch+2 load first (its buffer was freed after compute of
        // ch-1 and the trailing barrier of the previous iteration)
        if (ch + 2 < GNCH) {
            gemm_load_chunk(sb + (uint32_t)((ch + 2) % 3) * STG_SZ,
                            Ahi, Alo, Bhi, rowBase, colBase, (ch + 2) * GBK, tid);
            cp_wait<2>();
        } else if (ch + 1 < GNCH) {
            cp_wait<1>();
        } else {
            cp_wait<0>();
        }
        __syncthreads();
        const uint32_t buf = sb + (uint32_t)(ch % 3) * STG_SZ;

#pragma unroll
        for (int k16 = 0; k16 < 2; k16++) {
            const uint32_t kb = (uint32_t)(k16 * 32);
            uint32_t ah[4][4], al[4][4];
#pragma unroll
            for (int mt = 0; mt < 4; mt++) {
                uint32_t ao = buf + a_lane + kb + (uint32_t)(mt * 16 * ROWB);
                ldm_x4(ah[mt], ao + OFF_AHI);
                ldm_x4(al[mt], ao + OFF_ALO);
            }
            uint32_t bh[2][4];
#pragma unroll
            for (int half = 0; half < 2; half++) {
                uint32_t bo = buf + b_lane + kb + (uint32_t)(half * 16 * ROWB);
                ldm_x4(bh[half], bo + OFF_BHI);
            }
#pragma unroll
            for (int mt = 0; mt < 4; mt++)
#pragma unroll
                for (int nt = 0; nt < 4; nt++) {
                    const uint32_t* bhf = &bh[nt >> 1][(nt & 1) * 2];
                    mma16816h(acc[mt][nt], ah[mt], bhf);
                    mma16816h(acc[mt][nt], al[mt], bhf);
                }
        }
        __syncthreads();
    }

#pragma unroll
    for (int mt = 0; mt < 4; mt++) {
        const int row0 = rowBase + warpM * 64 + mt * 16 + (lane >> 2);
#pragma unroll
        for (int nt = 0; nt < 4; nt++) {
            const int col = colBase + warpN * 32 + nt * 8 + (lane & 3) * 2;
            float b0 = 0.f, b1 = 0.f;
            if (bias != nullptr) { b0 = bias[col]; b1 = bias[col + 1]; }
            float2 v0 = make_float2(acc[mt][nt][0] + b0, acc[mt][nt][1] + b1);
            float2 v1 = make_float2(acc[mt][nt][2] + b0, acc[mt][nt][3] + b1);
            *(float2*)&C[(size_t)row0 * N + col]       = v0;
            *(float2*)&C[(size_t)(row0 + 8) * N + col] = v1;
        }
    }
}

// ---------------------------------------------------------------------------
// fp32 -> fp16 hi/lo elementwise split (for x)
// ---------------------------------------------------------------------------
__global__ void split_fp32(const float* __restrict__ src,
                           __half* __restrict__ hi,
                           __half* __restrict__ lo, size_t n4)
{
    size_t i = (size_t)blockIdx.x * blockDim.x + threadIdx.x;
    if (i >= n4) return;
    float4 v = ((const float4*)src)[i];
    __half h0 = __float2half(v.x);
    __half h1 = __float2half(v.y);
    __half h2 = __float2half(v.z);
    __half h3 = __float2half(v.w);
    __half2* hp = (__half2*)hi;
    __half2* lp = (__half2*)lo;
    hp[i * 2 + 0] = __halves2half2(h0, h1);
    hp[i * 2 + 1] = __halves2half2(h2, h3);
    lp[i * 2 + 0] = __halves2half2(__float2half(v.x - __half2float(h0)),
                                   __float2half(v.y - __half2float(h1)));
    lp[i * 2 + 1] = __halves2half2(__float2half(v.z - __half2float(h2)),
                                   __float2half(v.w - __half2float(h3)));
}

// ---------------------------------------------------------------------------
// W [K,N] row-major -> [N,K] K-major fp16 (transpose + round, hi only)
// ---------------------------------------------------------------------------
__global__ void transpose_round(const float* __restrict__ W,
                                __half* __restrict__ hi, int K, int N)
{
    __shared__ float t[32][33];
    int n0 = blockIdx.x * 32, k0 = blockIdx.y * 32;
    for (int r = threadIdx.y; r < 32; r += 8)
        t[r][threadIdx.x] = W[(size_t)(k0 + r) * N + n0 + threadIdx.x];
    __syncthreads();
    for (int r = threadIdx.y; r < 32; r += 8) {
        float v = t[threadIdx.x][r];
        hi[(size_t)(n0 + r) * K + k0 + threadIdx.x] = __float2half(v);
    }
}

// ---------------------------------------------------------------------------
// Fused MMA attention (R5, unchanged math): bf16 hi/lo 3-term, two-pass
// exact softmax, 13 warps/CTA. Epilogue now emits fp16 hi/lo for stage 3.
// ---------------------------------------------------------------------------
#define QK_ROWB 144
#define VT_ROWB 432
#define SQ_HI  0
#define SQ_LO  29952
#define SK_HI  59904
#define SK_LO  89856
#define SV_HI  119808
#define SV_LO  147456
#define ATT_SMEM 175104
#define ATT_THREADS 416

__global__ void __launch_bounds__(ATT_THREADS, 1)
win_attn_mma()
{
    const uint32_t sb = smem_u32(smem_raw);
    const int l    = blockIdx.x;
    const int head = blockIdx.y;
    const int b    = blockIdx.z;
    const int wy   = l / NW_WIN;
    const int wx   = l % NW_WIN;
    const int tid  = threadIdx.x;
    const int lane = tid & 31;
    const int w    = tid >> 5;       // 0..12

    // ---- load Q (scaled) and K into smem as bf16 hi/lo ----
#pragma unroll
    for (int it = 0; it < 8; it++) {
        int idx = tid + it * ATT_THREADS;
        int row = idx >> 4;
        int d4  = (idx & 15) * 4;
        int rr = row / WIN, cc = row % WIN;
        int hh = wy * WIN + rr, ww = wx * WIN + cc;
        bool valid = (row < NWTOK) && (hh < H_IMG) && (ww < W_IMG);
        float4 qv = make_float4(0.f, 0.f, 0.f, 0.f);
        float4 kv = qv;
        if (valid) {
            size_t base = ((size_t)(b * NTOK + hh * W_IMG + ww)) * QKV_DIM
                          + (size_t)head * HDIM + d4;
            qv = *(const float4*)&g_qkv[base];
            kv = *(const float4*)&g_qkv[base + C_DIM];
            qv.x *= 0.125f; qv.y *= 0.125f; qv.z *= 0.125f; qv.w *= 0.125f;
        }
        uint32_t off = (uint32_t)(row * QK_ROWB + d4 * 2);
        {
            __nv_bfloat16 h0 = __float2bfloat16(qv.x), h1 = __float2bfloat16(qv.y);
            __nv_bfloat16 h2 = __float2bfloat16(qv.z), h3 = __float2bfloat16(qv.w);
            *(__nv_bfloat162*)(smem_raw + SQ_HI + off)     = __nv_bfloat162(h0, h1);
            *(__nv_bfloat162*)(smem_raw + SQ_HI + off + 4) = __nv_bfloat162(h2, h3);
            *(__nv_bfloat162*)(smem_raw + SQ_LO + off)     = __nv_bfloat162(
                __float2bfloat16(qv.x - __bfloat162float(h0)),
                __float2bfloat16(qv.y - __bfloat162float(h1)));
            *(__nv_bfloat162*)(smem_raw + SQ_LO + off + 4) = __nv_bfloat162(
                __float2bfloat16(qv.z - __bfloat162float(h2)),
                __float2bfloat16(qv.w - __bfloat162float(h3)));
        }
        {
            __nv_bfloat16 h0 = __float2bfloat16(kv.x), h1 = __float2bfloat16(kv.y);
            __nv_bfloat16 h2 = __float2bfloat16(kv.z), h3 = __float2bfloat16(kv.w);
            *(__nv_bfloat162*)(smem_raw + SK_HI + off)     = __nv_bfloat162(h0, h1);
            *(__nv_bfloat162*)(smem_raw + SK_HI + off + 4) = __nv_bfloat162(h2, h3);
            *(__nv_bfloat162*)(smem_raw + SK_LO + off)     = __nv_bfloat162(
                __float2bfloat16(kv.x - __bfloat162float(h0)),
                __float2bfloat16(kv.y - __bfloat162float(h1)));
            *(__nv_bfloat162*)(smem_raw + SK_LO + off + 4) = __nv_bfloat162(
                __float2bfloat16(kv.z - __bfloat162float(h2)),
                __float2bfloat16(kv.w - __bfloat162float(h3)));
        }
    }
    // ---- load V transposed: V^T[d][key] ----
#pragma unroll
    for (int it = 0; it < 8; it++) {
        int idx = tid + it * ATT_THREADS;
        int j  = idx >> 4;
        int d4 = (idx & 15) * 4;
        int rr = j / WIN, cc = j % WIN;
        int hh = wy * WIN + rr, ww = wx * WIN + cc;
        bool valid = (j < NWTOK) && (hh < H_IMG) && (ww < W_IMG);
        float4 vv = make_float4(0.f, 0.f, 0.f, 0.f);
        if (valid) {
            size_t base = ((size_t)(b * NTOK + hh * W_IMG + ww)) * QKV_DIM
                          + (size_t)head * HDIM + d4 + 2 * C_DIM;
            vv = *(const float4*)&g_qkv[base];
        }
        float ve[4] = {vv.x, vv.y, vv.z, vv.w};
#pragma unroll
        for (int e = 0; e < 4; e++) {
            __nv_bfloat16 h = __float2bfloat16(ve[e]);
            uint32_t off = (uint32_t)((d4 + e) * VT_ROWB + j * 2);
            *(__nv_bfloat16*)(smem_raw + SV_HI + off) = h;
            *(__nv_bfloat16*)(smem_raw + SV_LO + off) =
                __float2bfloat16(ve[e] - __bfloat162float(h));
        }
    }
    __syncthreads();

    const uint32_t a_lane  = sb + (uint32_t)((w * 16 + (lane & 15)) * QK_ROWB + (lane >> 4) * 16);
    const uint32_t kb_lane = sb + SK_HI
        + (uint32_t)((((lane & 7) | ((lane >> 4) << 3))) * QK_ROWB + ((lane >> 3) & 1) * 16);
    const uint32_t vb_lane = sb + SV_HI
        + (uint32_t)((((lane & 7) | ((lane >> 4) << 3))) * VT_ROWB + ((lane >> 3) & 1) * 16);

    uint32_t qah[4][4], qal[4][4];
#pragma unroll
    for (int kt = 0; kt < 4; kt++) {
        ldm_x4(qah[kt], a_lane + SQ_HI + kt * 32);
        ldm_x4(qal[kt], a_lane + SQ_LO + kt * 32);
    }

    const int cq = 2 * (lane & 3);

    // ---- pass 1: row max ----
    float m0 = -1e30f, m1 = -1e30f;
    for (int t = 0; t < 13; t++) {
        uint32_t kbh[4][4], kbl[4][4];
#pragma unroll
        for (int kt = 0; kt < 4; kt++) {
            uint32_t addr = kb_lane + (uint32_t)(t * 16 * QK_ROWB + kt * 32);
            ldm_x4(kbh[kt], addr);
            ldm_x4(kbl[kt], addr + (SK_LO - SK_HI));
        }
        float s0[4] = {0.f, 0.f, 0.f, 0.f}, s1[4] = {0.f, 0.f, 0.f, 0.f};
#pragma unroll
        for (int kt = 0; kt < 4; kt++) {
            mma16816(s0, qah[kt], &kbh[kt][0]);
            mma16816(s0, qah[kt], &kbl[kt][0]);
            mma16816(s0, qal[kt], &kbh[kt][0]);
            mma16816(s1, qah[kt], &kbh[kt][2]);
            mma16816(s1, qah[kt], &kbl[kt][2]);
            mma16816(s1, qal[kt], &kbh[kt][2]);
        }
        int j0 = t * 16 + cq;
        int j1 = j0 + 8;
        if (j0     < NWTOK) { m0 = fmaxf(m0, s0[0]); m1 = fmaxf(m1, s0[2]); }
        if (j0 + 1 < NWTOK) { m0 = fmaxf(m0, s0[1]); m1 = fmaxf(m1, s0[3]); }
        if (j1     < NWTOK) { m0 = fmaxf(m0, s1[0]); m1 = fmaxf(m1, s1[2]); }
        if (j1 + 1 < NWTOK) { m0 = fmaxf(m0, s1[1]); m1 = fmaxf(m1, s1[3]); }
    }
#pragma unroll
    for (int off = 1; off <= 2; off <<= 1) {
        m0 = fmaxf(m0, __shfl_xor_sync(0xffffffffu, m0, off));
        m1 = fmaxf(m1, __shfl_xor_sync(0xffffffffu, m1, off));
    }

    // ---- pass 2 ----
    float o[8][4];
#pragma unroll
    for (int i = 0; i < 8; i++)
#pragma unroll
        for (int e = 0; e < 4; e++) o[i][e] = 0.f;
    float sum0 = 0.f, sum1 = 0.f;

    for (int t = 0; t < 13; t++) {
        uint32_t kbh[4][4], kbl[4][4];
#pragma unroll
        for (int kt = 0; kt < 4; kt++) {
            uint32_t addr = kb_lane + (uint32_t)(t * 16 * QK_ROWB + kt * 32);
            ldm_x4(kbh[kt], addr);
            ldm_x4(kbl[kt], addr + (SK_LO - SK_HI));
        }
        float s0[4] = {0.f, 0.f, 0.f, 0.f}, s1[4] = {0.f, 0.f, 0.f, 0.f};
#pragma unroll
        for (int kt = 0; kt < 4; kt++) {
            mma16816(s0, qah[kt], &kbh[kt][0]);
            mma16816(s0, qah[kt], &kbl[kt][0]);
            mma16816(s0, qal[kt], &kbh[kt][0]);
            mma16816(s1, qah[kt], &kbh[kt][2]);
            mma16816(s1, qah[kt], &kbl[kt][2]);
            mma16816(s1, qal[kt], &kbh[kt][2]);
        }
        int j0 = t * 16 + cq;
        int j1 = j0 + 8;
        float p0 = (j0     < NWTOK) ? __expf(s0[0] - m0) : 0.f;
        float p1 = (j0 + 1 < NWTOK) ? __expf(s0[1] - m0) : 0.f;
        float p2 = (j0     < NWTOK) ? __expf(s0[2] - m1) : 0.f;
        float p3 = (j0 + 1 < NWTOK) ? __expf(s0[3] - m1) : 0.f;
        float u0 = (j1     < NWTOK) ? __expf(s1[0] - m0) : 0.f;
        float u1 = (j1 + 1 < NWTOK) ? __expf(s1[1] - m0) : 0.f;
        float u2 = (j1     < NWTOK) ? __expf(s1[2] - m1) : 0.f;
        float u3 = (j1 + 1 < NWTOK) ? __expf(s1[3] - m1) : 0.f;
        sum0 += p0 + p1 + u0 + u1;
        sum1 += p2 + p3 + u2 + u3;

        float h0 = __bfloat162float(__float2bfloat16(p0));
        float h1 = __bfloat162float(__float2bfloat16(p1));
        float h2 = __bfloat162float(__float2bfloat16(p2));
        float h3 = __bfloat162float(__float2bfloat16(p3));
        float g0 = __bfloat162float(__float2bfloat16(u0));
        float g1 = __bfloat162float(__float2bfloat16(u1));
        float g2 = __bfloat162float(__float2bfloat16(u2));
        float g3 = __bfloat162float(__float2bfloat16(u3));
        uint32_t pah[4], pal[4];
        pah[0] = pack_bf16(p0, p1);   pah[1] = pack_bf16(p2, p3);
        pah[2] = pack_bf16(u0, u1);   pah[3] = pack_bf16(u2, u3);
        pal[0] = pack_bf16(p0 - h0, p1 - h1);
        pal[1] = pack_bf16(p2 - h2, p3 - h3);
        pal[2] = pack_bf16(u0 - g0, u1 - g1);
        pal[3] = pack_bf16(u2 - g2, u3 - g3);

#pragma unroll
        for (int dg = 0; dg < 4; dg++) {
            uint32_t vbh[4], vbl[4];
            uint32_t addr = vb_lane + (uint32_t)(dg * 16 * VT_ROWB + t * 32);
            ldm_x4(vbh, addr);
            ldm_x4(vbl, addr + (SV_LO - SV_HI));
            mma16816(o[dg * 2 + 0], pah, &vbh[0]);
            mma16816(o[dg * 2 + 0], pah, &vbl[0]);
            mma16816(o[dg * 2 + 0], pal, &vbh[0]);
            mma16816(o[dg * 2 + 1], pah, &vbh[2]);
            mma16816(o[dg * 2 + 1], pah, &vbl[2]);
            mma16816(o[dg * 2 + 1], pal, &vbh[2]);
        }
    }
#pragma unroll
    for (int off = 1; off <= 2; off <<= 1) {
        sum0 += __shfl_xor_sync(0xffffffffu, sum0, off);
        sum1 += __shfl_xor_sync(0xffffffffu, sum1, off);
    }
    const float inv0 = 1.f / sum0;
    const float inv1 = 1.f / sum1;

    // ---- epilogue: O/sum -> g_atthi/lo (fp16 hi/lo split) ----
    const int r0 = w * 16 + (lane >> 2);
#pragma unroll
    for (int half = 0; half < 2; half++) {
        const int row = r0 + half * 8;
        if (row >= NWTOK) continue;
        const int rr = row / WIN, cc = row % WIN;
        const int hh = wy * WIN + rr, ww = wx * WIN + cc;
        if (hh >= H_IMG || ww >= W_IMG) continue;
        const float inv = half ? inv1 : inv0;
        const size_t obase = ((size_t)(b * NTOK + hh * W_IMG + ww)) * C_DIM
                             + (size_t)head * HDIM;
#pragma unroll
        for (int dt = 0; dt < 8; dt++) {
            const int col = dt * 8 + cq;
            float v0 = o[dt][half * 2 + 0] * inv;
            float v1 = o[dt][half * 2 + 1] * inv;
            __half h0 = __float2half(v0);
            __half h1 = __float2half(v1);
            *(__half2*)&g_atthi[obase + col] = __halves2half2(h0, h1);
            *(__half2*)&g_attlo[obase + col] = __halves2half2(
                __float2half(v0 - __half2float(h0)),
                __float2half(v1 - __half2float(h1)));
        }
    }
}

// ---------------------------------------------------------------------------
// Launch
// ---------------------------------------------------------------------------
extern "C" void kernel_launch(void* const* d_in, const int* in_sizes, int n_in,
                              void* d_out, int out_size)
{
    const float* x     = (const float*)d_in[0];
    const float* Wqkv  = (const float*)d_in[1];
    const float* Wproj = (const float*)d_in[2];
    const float* bproj = (const float*)d_in[3];
    float* out = (float*)d_out;

    float *qkvp;
    __half *xhi, *xlo, *wqh, *wph, *athi, *atlo;
    cudaGetSymbolAddress((void**)&qkvp, g_qkv);
    cudaGetSymbolAddress((void**)&xhi,  g_xhi);
    cudaGetSymbolAddress((void**)&xlo,  g_xlo);
    cudaGetSymbolAddress((void**)&wqh,  g_wqkv_hi);
    cudaGetSymbolAddress((void**)&wph,  g_wproj_hi);
    cudaGetSymbolAddress((void**)&athi, g_atthi);
    cudaGetSymbolAddress((void**)&atlo, g_attlo);

    // convert x + weights to fp16
    {
        size_t n4 = (size_t)MTOT * C_DIM / 4;
        split_fp32<<<(unsigned)((n4 + 255) / 256), 256>>>(x, xhi, xlo, n4);
        transpose_round<<<dim3(QKV_DIM / 32, C_DIM / 32), dim3(32, 8)>>>(Wqkv, wqh, C_DIM, QKV_DIM);
        transpose_round<<<dim3(C_DIM / 32,  C_DIM / 32), dim3(32, 8)>>>(Wproj, wph, C_DIM, C_DIM);
    }

    cudaFuncSetAttribute(wmma_gemm, cudaFuncAttributeMaxDynamicSharedMemorySize, GEMM_SMEM);
    cudaFuncSetAttribute(win_attn_mma, cudaFuncAttributeMaxDynamicSharedMemorySize, ATT_SMEM);

    // Stage 1: qkv = x @ Wqkv
    wmma_gemm<<<dim3(QKV_DIM / GBN, MTOT / GBM), 256, GEMM_SMEM>>>(
        xhi, xlo, wqh, nullptr, qkvp, QKV_DIM);

    // Stage 2: fused MMA attention
    win_attn_mma<<<dim3(LWIN, NHEADS, B_SZ), ATT_THREADS, ATT_SMEM>>>();

    // Stage 3: out = att @ Wproj + bproj
    wmma_gemm<<<dim3(C_DIM / GBN, MTOT / GBM), 256, GEMM_SMEM>>>(
        athi, atlo, wph, bproj, out, C_DIM);
}

// round 8
// speedup vs baseline: 4.5655x; 1.2660x over previous
#include <cuda_runtime.h>
#include <cuda_bf16.h>
#include <cuda_fp16.h>
#include <math.h>
#include <stdint.h>

// ---------------------------------------------------------------------------
// WindowedAttention on GB300 (sm_103a chip; ptxas target is base sm_103 so
// tcgen05 unavailable — warp-level mma.sync tensor cores).
// R8: stage 1 plain fp16 GEMM (error attenuated through softmax);
//     stage 3 fp16 2-term split ((A_hi+A_lo) @ B_hi);
//     single-__syncthreads 3-stage cp.async pipeline;
//     attention bf16 3-term two-pass MMA (R5 design).
// ---------------------------------------------------------------------------

#define C_DIM    768
#define QKV_DIM  2304
#define B_SZ     8
#define H_IMG    80
#define W_IMG    80
#define NTOK     (H_IMG * W_IMG)     // 6400
#define WIN      14
#define NW_WIN   6
#define LWIN     36
#define NWTOK    (WIN * WIN)         // 196
#define NHEADS   12
#define HDIM     64
#define MTOT     (B_SZ * NTOK)       // 51200

// ---------------- scratch (__device__ globals: allocation-free rule) -------
__device__ float   g_qkv[(size_t)MTOT * QKV_DIM];      // fp32 qkv
__device__ __half  g_xhi[(size_t)MTOT * C_DIM];
__device__ __half  g_wqkv_hi[(size_t)QKV_DIM * C_DIM]; // [N,K] K-major
__device__ __half  g_wproj_hi[(size_t)C_DIM * C_DIM];  // [N,K] K-major
__device__ __half  g_atthi[(size_t)MTOT * C_DIM];
__device__ __half  g_attlo[(size_t)MTOT * C_DIM];

extern __shared__ char smem_raw[];

// ---------------------------- PTX helpers ----------------------------------
__device__ __forceinline__ uint32_t smem_u32(const void* p) {
    uint32_t a;
    asm("{ .reg .u64 t; cvta.to.shared.u64 t, %1; cvt.u32.u64 %0, t; }"
        : "=r"(a) : "l"(p));
    return a;
}
__device__ __forceinline__ void cp16(uint32_t saddr, const void* g) {
    asm volatile("cp.async.cg.shared.global [%0], [%1], 16;" :: "r"(saddr), "l"(g));
}
__device__ __forceinline__ void cp_commit() { asm volatile("cp.async.commit_group;" ::: "memory"); }
template <int N> __device__ __forceinline__ void cp_wait() {
    asm volatile("cp.async.wait_group %0;" :: "n"(N) : "memory");
}
__device__ __forceinline__ void ldm_x4(uint32_t* r, uint32_t addr) {
    asm volatile("ldmatrix.sync.aligned.m8n8.x4.shared.b16 {%0,%1,%2,%3}, [%4];"
        : "=r"(r[0]), "=r"(r[1]), "=r"(r[2]), "=r"(r[3]) : "r"(addr));
}
// bf16 MMA (attention)
__device__ __forceinline__ void mma16816(float* d, const uint32_t* a, const uint32_t* b) {
    asm volatile(
        "mma.sync.aligned.m16n8k16.row.col.f32.bf16.bf16.f32 "
        "{%0,%1,%2,%3}, {%4,%5,%6,%7}, {%8,%9}, {%0,%1,%2,%3};"
        : "+f"(d[0]), "+f"(d[1]), "+f"(d[2]), "+f"(d[3])
        : "r"(a[0]), "r"(a[1]), "r"(a[2]), "r"(a[3]), "r"(b[0]), "r"(b[1]));
}
// fp16 MMA (GEMMs)
__device__ __forceinline__ void mma16816h(float* d, const uint32_t* a, const uint32_t* b) {
    asm volatile(
        "mma.sync.aligned.m16n8k16.row.col.f32.f16.f16.f32 "
        "{%0,%1,%2,%3}, {%4,%5,%6,%7}, {%8,%9}, {%0,%1,%2,%3};"
        : "+f"(d[0]), "+f"(d[1]), "+f"(d[2]), "+f"(d[3])
        : "r"(a[0]), "r"(a[1]), "r"(a[2]), "r"(a[3]), "r"(b[0]), "r"(b[1]));
}
__device__ __forceinline__ uint32_t pack_bf16(float lo, float hi) {
    uint32_t r;
    asm("cvt.rn.bf16x2.f32 %0, %1, %2;" : "=r"(r) : "f"(hi), "f"(lo));
    return r;
}

// ---------------------------------------------------------------------------
// Warp-MMA GEMM: C[M,N] = A[M,768] @ B[N,768]^T (+ bias), fp16 operands.
// USE_ALO=true adds the (A_lo @ B_hi) correction term (2-term split).
// BM=BN=128, BK=32, 8 warps (2x4), warp tile 64x32, 3-stage cp.async with
// a single __syncthreads per chunk.
// ---------------------------------------------------------------------------
#define GBM 128
#define GBN 128
#define GBK 32
#define GNCH (768 / GBK)         // 24
#define ROWB 80                  // smem row stride bytes (32 halves + 8 pad)
#define OFF_ALO 10240

template <bool USE_ALO>
__device__ __forceinline__ void gemm_load_chunk(
    uint32_t buf,
    const __half* __restrict__ Ahi, const __half* __restrict__ Alo,
    const __half* __restrict__ Bhi,
    int rowBase, int colBase, int k0, int tid)
{
    constexpr uint32_t OFF_BHI_T = USE_ALO ? 20480u : 10240u;
#pragma unroll
    for (int it = 0; it < 2; it++) {
        int t = tid + it * 256;           // 0..511
        int r = t >> 2;                   // row 0..127
        int c = t & 3;                    // 16B unit 0..3
        uint32_t soff = (uint32_t)(r * ROWB + c * 16);
        size_t ga = (size_t)(rowBase + r) * 768 + k0 + c * 8;
        size_t gb = (size_t)(colBase + r) * 768 + k0 + c * 8;
        cp16(buf + soff, Ahi + ga);
        if (USE_ALO) cp16(buf + OFF_ALO + soff, Alo + ga);
        cp16(buf + OFF_BHI_T + soff, Bhi + gb);
    }
    cp_commit();
}

template <bool USE_ALO>
__global__ void __launch_bounds__(256)
wmma_gemm(const __half* __restrict__ Ahi, const __half* __restrict__ Alo,
          const __half* __restrict__ Bhi,
          const float* __restrict__ bias, float* __restrict__ C, int N)
{
    constexpr uint32_t OFF_BHI_T = USE_ALO ? 20480u : 10240u;
    constexpr uint32_t STG = USE_ALO ? 30720u : 20480u;

    const uint32_t sb = smem_u32(smem_raw);
    const int tid   = threadIdx.x;
    const int lane  = tid & 31;
    const int wid   = tid >> 5;
    const int warpM = wid >> 2;
    const int warpN = wid & 3;
    const int rowBase = blockIdx.y * GBM;
    const int colBase = blockIdx.x * GBN;

    float acc[4][4][4];
#pragma unroll
    for (int i = 0; i < 4; i++)
#pragma unroll
        for (int j = 0; j < 4; j++)
#pragma unroll
            for (int e = 0; e < 4; e++) acc[i][j][e] = 0.f;

    const uint32_t a_lane = (uint32_t)((warpM * 64 + (lane & 15)) * ROWB + (lane >> 4) * 16);
    const uint32_t b_lane = (uint32_t)((warpN * 32 + ((lane & 7) | ((lane >> 4) << 3))) * ROWB
                                       + ((lane >> 3) & 1) * 16);

    gemm_load_chunk<USE_ALO>(sb,       Ahi, Alo, Bhi, rowBase, colBase, 0,   tid);
    gemm_load_chunk<USE_ALO>(sb + STG, Ahi, Alo, Bhi, rowBase, colBase, GBK, tid);

    for (int ch = 0; ch < GNCH; ch++) {
        if (ch < GNCH - 1) cp_wait<1>(); else cp_wait<0>();
        __syncthreads();
        // safe: the sync above proves all warps finished compute(ch-1),
        // which is the last consumer of buffer (ch+2)%3.
        if (ch + 2 < GNCH)
            gemm_load_chunk<USE_ALO>(sb + (uint32_t)((ch + 2) % 3) * STG,
                                     Ahi, Alo, Bhi, rowBase, colBase,
                                     (ch + 2) * GBK, tid);
        const uint32_t buf = sb + (uint32_t)(ch % 3) * STG;

#pragma unroll
        for (int k16 = 0; k16 < 2; k16++) {
            const uint32_t kb = (uint32_t)(k16 * 32);
            uint32_t ah[4][4], al[4][4];
#pragma unroll
            for (int mt = 0; mt < 4; mt++) {
                uint32_t ao = buf + a_lane + kb + (uint32_t)(mt * 16 * ROWB);
                ldm_x4(ah[mt], ao);
                if (USE_ALO) ldm_x4(al[mt], ao + OFF_ALO);
            }
            uint32_t bh[2][4];
#pragma unroll
            for (int half = 0; half < 2; half++) {
                uint32_t bo = buf + b_lane + kb + (uint32_t)(half * 16 * ROWB);
                ldm_x4(bh[half], bo + OFF_BHI_T);
            }
#pragma unroll
            for (int mt = 0; mt < 4; mt++)
#pragma unroll
                for (int nt = 0; nt < 4; nt++) {
                    const uint32_t* bhf = &bh[nt >> 1][(nt & 1) * 2];
                    mma16816h(acc[mt][nt], ah[mt], bhf);
                    if (USE_ALO) mma16816h(acc[mt][nt], al[mt], bhf);
                }
        }
    }

#pragma unroll
    for (int mt = 0; mt < 4; mt++) {
        const int row0 = rowBase + warpM * 64 + mt * 16 + (lane >> 2);
#pragma unroll
        for (int nt = 0; nt < 4; nt++) {
            const int col = colBase + warpN * 32 + nt * 8 + (lane & 3) * 2;
            float b0 = 0.f, b1 = 0.f;
            if (bias != nullptr) { b0 = bias[col]; b1 = bias[col + 1]; }
            float2 v0 = make_float2(acc[mt][nt][0] + b0, acc[mt][nt][1] + b1);
            float2 v1 = make_float2(acc[mt][nt][2] + b0, acc[mt][nt][3] + b1);
            *(float2*)&C[(size_t)row0 * N + col]       = v0;
            *(float2*)&C[(size_t)(row0 + 8) * N + col] = v1;
        }
    }
}

// ---------------------------------------------------------------------------
// fp32 -> fp16 round (for x; stage-1 uses plain fp16 A)
// ---------------------------------------------------------------------------
__global__ void round_fp32(const float* __restrict__ src,
                           __half* __restrict__ hi, size_t n4)
{
    size_t i = (size_t)blockIdx.x * blockDim.x + threadIdx.x;
    if (i >= n4) return;
    float4 v = ((const float4*)src)[i];
    __half2* hp = (__half2*)hi;
    hp[i * 2 + 0] = __halves2half2(__float2half(v.x), __float2half(v.y));
    hp[i * 2 + 1] = __halves2half2(__float2half(v.z), __float2half(v.w));
}

// ---------------------------------------------------------------------------
// W [K,N] row-major -> [N,K] K-major fp16 (transpose + round)
// ---------------------------------------------------------------------------
__global__ void transpose_round(const float* __restrict__ W,
                                __half* __restrict__ hi, int K, int N)
{
    __shared__ float t[32][33];
    int n0 = blockIdx.x * 32, k0 = blockIdx.y * 32;
    for (int r = threadIdx.y; r < 32; r += 8)
        t[r][threadIdx.x] = W[(size_t)(k0 + r) * N + n0 + threadIdx.x];
    __syncthreads();
    for (int r = threadIdx.y; r < 32; r += 8) {
        float v = t[threadIdx.x][r];
        hi[(size_t)(n0 + r) * K + k0 + threadIdx.x] = __float2half(v);
    }
}

// ---------------------------------------------------------------------------
// Fused MMA attention (R5, unchanged math): bf16 hi/lo 3-term, two-pass
// exact softmax, 13 warps/CTA. Epilogue emits fp16 hi/lo for stage 3.
// ---------------------------------------------------------------------------
#define QK_ROWB 144
#define VT_ROWB 432
#define SQ_HI  0
#define SQ_LO  29952
#define SK_HI  59904
#define SK_LO  89856
#define SV_HI  119808
#define SV_LO  147456
#define ATT_SMEM 175104
#define ATT_THREADS 416

__global__ void __launch_bounds__(ATT_THREADS, 1)
win_attn_mma()
{
    const uint32_t sb = smem_u32(smem_raw);
    const int l    = blockIdx.x;
    const int head = blockIdx.y;
    const int b    = blockIdx.z;
    const int wy   = l / NW_WIN;
    const int wx   = l % NW_WIN;
    const int tid  = threadIdx.x;
    const int lane = tid & 31;
    const int w    = tid >> 5;       // 0..12

    // ---- load Q (scaled) and K into smem as bf16 hi/lo ----
#pragma unroll
    for (int it = 0; it < 8; it++) {
        int idx = tid + it * ATT_THREADS;
        int row = idx >> 4;
        int d4  = (idx & 15) * 4;
        int rr = row / WIN, cc = row % WIN;
        int hh = wy * WIN + rr, ww = wx * WIN + cc;
        bool valid = (row < NWTOK) && (hh < H_IMG) && (ww < W_IMG);
        float4 qv = make_float4(0.f, 0.f, 0.f, 0.f);
        float4 kv = qv;
        if (valid) {
            size_t base = ((size_t)(b * NTOK + hh * W_IMG + ww)) * QKV_DIM
                          + (size_t)head * HDIM + d4;
            qv = *(const float4*)&g_qkv[base];
            kv = *(const float4*)&g_qkv[base + C_DIM];
            qv.x *= 0.125f; qv.y *= 0.125f; qv.z *= 0.125f; qv.w *= 0.125f;
        }
        uint32_t off = (uint32_t)(row * QK_ROWB + d4 * 2);
        {
            __nv_bfloat16 h0 = __float2bfloat16(qv.x), h1 = __float2bfloat16(qv.y);
            __nv_bfloat16 h2 = __float2bfloat16(qv.z), h3 = __float2bfloat16(qv.w);
            *(__nv_bfloat162*)(smem_raw + SQ_HI + off)     = __nv_bfloat162(h0, h1);
            *(__nv_bfloat162*)(smem_raw + SQ_HI + off + 4) = __nv_bfloat162(h2, h3);
            *(__nv_bfloat162*)(smem_raw + SQ_LO + off)     = __nv_bfloat162(
                __float2bfloat16(qv.x - __bfloat162float(h0)),
                __float2bfloat16(qv.y - __bfloat162float(h1)));
            *(__nv_bfloat162*)(smem_raw + SQ_LO + off + 4) = __nv_bfloat162(
                __float2bfloat16(qv.z - __bfloat162float(h2)),
                __float2bfloat16(qv.w - __bfloat162float(h3)));
        }
        {
            __nv_bfloat16 h0 = __float2bfloat16(kv.x), h1 = __float2bfloat16(kv.y);
            __nv_bfloat16 h2 = __float2bfloat16(kv.z), h3 = __float2bfloat16(kv.w);
            *(__nv_bfloat162*)(smem_raw + SK_HI + off)     = __nv_bfloat162(h0, h1);
            *(__nv_bfloat162*)(smem_raw + SK_HI + off + 4) = __nv_bfloat162(h2, h3);
            *(__nv_bfloat162*)(smem_raw + SK_LO + off)     = __nv_bfloat162(
                __float2bfloat16(kv.x - __bfloat162float(h0)),
                __float2bfloat16(kv.y - __bfloat162float(h1)));
            *(__nv_bfloat162*)(smem_raw + SK_LO + off + 4) = __nv_bfloat162(
                __float2bfloat16(kv.z - __bfloat162float(h2)),
                __float2bfloat16(kv.w - __bfloat162float(h3)));
        }
    }
    // ---- load V transposed: V^T[d][key] ----
#pragma unroll
    for (int it = 0; it < 8; it++) {
        int idx = tid + it * ATT_THREADS;
        int j  = idx >> 4;
        int d4 = (idx & 15) * 4;
        int rr = j / WIN, cc = j % WIN;
        int hh = wy * WIN + rr, ww = wx * WIN + cc;
        bool valid = (j < NWTOK) && (hh < H_IMG) && (ww < W_IMG);
        float4 vv = make_float4(0.f, 0.f, 0.f, 0.f);
        if (valid) {
            size_t base = ((size_t)(b * NTOK + hh * W_IMG + ww)) * QKV_DIM
                          + (size_t)head * HDIM + d4 + 2 * C_DIM;
            vv = *(const float4*)&g_qkv[base];
        }
        float ve[4] = {vv.x, vv.y, vv.z, vv.w};
#pragma unroll
        for (int e = 0; e < 4; e++) {
            __nv_bfloat16 h = __float2bfloat16(ve[e]);
            uint32_t off = (uint32_t)((d4 + e) * VT_ROWB + j * 2);
            *(__nv_bfloat16*)(smem_raw + SV_HI + off) = h;
            *(__nv_bfloat16*)(smem_raw + SV_LO + off) =
                __float2bfloat16(ve[e] - __bfloat162float(h));
        }
    }
    __syncthreads();

    const uint32_t a_lane  = sb + (uint32_t)((w * 16 + (lane & 15)) * QK_ROWB + (lane >> 4) * 16);
    const uint32_t kb_lane = sb + SK_HI
        + (uint32_t)((((lane & 7) | ((lane >> 4) << 3))) * QK_ROWB + ((lane >> 3) & 1) * 16);
    const uint32_t vb_lane = sb + SV_HI
        + (uint32_t)((((lane & 7) | ((lane >> 4) << 3))) * VT_ROWB + ((lane >> 3) & 1) * 16);

    uint32_t qah[4][4], qal[4][4];
#pragma unroll
    for (int kt = 0; kt < 4; kt++) {
        ldm_x4(qah[kt], a_lane + SQ_HI + kt * 32);
        ldm_x4(qal[kt], a_lane + SQ_LO + kt * 32);
    }

    const int cq = 2 * (lane & 3);

    // ---- pass 1: row max ----
    float m0 = -1e30f, m1 = -1e30f;
    for (int t = 0; t < 13; t++) {
        uint32_t kbh[4][4], kbl[4][4];
#pragma unroll
        for (int kt = 0; kt < 4; kt++) {
            uint32_t addr = kb_lane + (uint32_t)(t * 16 * QK_ROWB + kt * 32);
            ldm_x4(kbh[kt], addr);
            ldm_x4(kbl[kt], addr + (SK_LO - SK_HI));
        }
        float s0[4] = {0.f, 0.f, 0.f, 0.f}, s1[4] = {0.f, 0.f, 0.f, 0.f};
#pragma unroll
        for (int kt = 0; kt < 4; kt++) {
            mma16816(s0, qah[kt], &kbh[kt][0]);
            mma16816(s0, qah[kt], &kbl[kt][0]);
            mma16816(s0, qal[kt], &kbh[kt][0]);
            mma16816(s1, qah[kt], &kbh[kt][2]);
            mma16816(s1, qah[kt], &kbl[kt][2]);
            mma16816(s1, qal[kt], &kbh[kt][2]);
        }
        int j0 = t * 16 + cq;
        int j1 = j0 + 8;
        if (j0     < NWTOK) { m0 = fmaxf(m0, s0[0]); m1 = fmaxf(m1, s0[2]); }
        if (j0 + 1 < NWTOK) { m0 = fmaxf(m0, s0[1]); m1 = fmaxf(m1, s0[3]); }
        if (j1     < NWTOK) { m0 = fmaxf(m0, s1[0]); m1 = fmaxf(m1, s1[2]); }
        if (j1 + 1 < NWTOK) { m0 = fmaxf(m0, s1[1]); m1 = fmaxf(m1, s1[3]); }
    }
#pragma unroll
    for (int off = 1; off <= 2; off <<= 1) {
        m0 = fmaxf(m0, __shfl_xor_sync(0xffffffffu, m0, off));
        m1 = fmaxf(m1, __shfl_xor_sync(0xffffffffu, m1, off));
    }

    // ---- pass 2 ----
    float o[8][4];
#pragma unroll
    for (int i = 0; i < 8; i++)
#pragma unroll
        for (int e = 0; e < 4; e++) o[i][e] = 0.f;
    float sum0 = 0.f, sum1 = 0.f;

    for (int t = 0; t < 13; t++) {
        uint32_t kbh[4][4], kbl[4][4];
#pragma unroll
        for (int kt = 0; kt < 4; kt++) {
            uint32_t addr = kb_lane + (uint32_t)(t * 16 * QK_ROWB + kt * 32);
            ldm_x4(kbh[kt], addr);
            ldm_x4(kbl[kt], addr + (SK_LO - SK_HI));
        }
        float s0[4] = {0.f, 0.f, 0.f, 0.f}, s1[4] = {0.f, 0.f, 0.f, 0.f};
#pragma unroll
        for (int kt = 0; kt < 4; kt++) {
            mma16816(s0, qah[kt], &kbh[kt][0]);
            mma16816(s0, qah[kt], &kbl[kt][0]);
            mma16816(s0, qal[kt], &kbh[kt][0]);
            mma16816(s1, qah[kt], &kbh[kt][2]);
            mma16816(s1, qah[kt], &kbl[kt][2]);
            mma16816(s1, qal[kt], &kbh[kt][2]);
        }
        int j0 = t * 16 + cq;
        int j1 = j0 + 8;
        float p0 = (j0     < NWTOK) ? __expf(s0[0] - m0) : 0.f;
        float p1 = (j0 + 1 < NWTOK) ? __expf(s0[1] - m0) : 0.f;
        float p2 = (j0     < NWTOK) ? __expf(s0[2] - m1) : 0.f;
        float p3 = (j0 + 1 < NWTOK) ? __expf(s0[3] - m1) : 0.f;
        float u0 = (j1     < NWTOK) ? __expf(s1[0] - m0) : 0.f;
        float u1 = (j1 + 1 < NWTOK) ? __expf(s1[1] - m0) : 0.f;
        float u2 = (j1     < NWTOK) ? __expf(s1[2] - m1) : 0.f;
        float u3 = (j1 + 1 < NWTOK) ? __expf(s1[3] - m1) : 0.f;
        sum0 += p0 + p1 + u0 + u1;
        sum1 += p2 + p3 + u2 + u3;

        float h0 = __bfloat162float(__float2bfloat16(p0));
        float h1 = __bfloat162float(__float2bfloat16(p1));
        float h2 = __bfloat162float(__float2bfloat16(p2));
        float h3 = __bfloat162float(__float2bfloat16(p3));
        float g0 = __bfloat162float(__float2bfloat16(u0));
        float g1 = __bfloat162float(__float2bfloat16(u1));
        float g2 = __bfloat162float(__float2bfloat16(u2));
        float g3 = __bfloat162float(__float2bfloat16(u3));
        uint32_t pah[4], pal[4];
        pah[0] = pack_bf16(p0, p1);   pah[1] = pack_bf16(p2, p3);
        pah[2] = pack_bf16(u0, u1);   pah[3] = pack_bf16(u2, u3);
        pal[0] = pack_bf16(p0 - h0, p1 - h1);
        pal[1] = pack_bf16(p2 - h2, p3 - h3);
        pal[2] = pack_bf16(u0 - g0, u1 - g1);
        pal[3] = pack_bf16(u2 - g2, u3 - g3);

#pragma unroll
        for (int dg = 0; dg < 4; dg++) {
            uint32_t vbh[4], vbl[4];
            uint32_t addr = vb_lane + (uint32_t)(dg * 16 * VT_ROWB + t * 32);
            ldm_x4(vbh, addr);
            ldm_x4(vbl, addr + (SV_LO - SV_HI));
            mma16816(o[dg * 2 + 0], pah, &vbh[0]);
            mma16816(o[dg * 2 + 0], pah, &vbl[0]);
            mma16816(o[dg * 2 + 0], pal, &vbh[0]);
            mma16816(o[dg * 2 + 1], pah, &vbh[2]);
            mma16816(o[dg * 2 + 1], pah, &vbl[2]);
            mma16816(o[dg * 2 + 1], pal, &vbh[2]);
        }
    }
#pragma unroll
    for (int off = 1; off <= 2; off <<= 1) {
        sum0 += __shfl_xor_sync(0xffffffffu, sum0, off);
        sum1 += __shfl_xor_sync(0xffffffffu, sum1, off);
    }
    const float inv0 = 1.f / sum0;
    const float inv1 = 1.f / sum1;

    // ---- epilogue: O/sum -> g_atthi/lo (fp16 hi/lo split) ----
    const int r0 = w * 16 + (lane >> 2);
#pragma unroll
    for (int half = 0; half < 2; half++) {
        const int row = r0 + half * 8;
        if (row >= NWTOK) continue;
        const int rr = row / WIN, cc = row % WIN;
        const int hh = wy * WIN + rr, ww = wx * WIN + cc;
        if (hh >= H_IMG || ww >= W_IMG) continue;
        const float inv = half ? inv1 : inv0;
        const size_t obase = ((size_t)(b * NTOK + hh * W_IMG + ww)) * C_DIM
                             + (size_t)head * HDIM;
#pragma unroll
        for (int dt = 0; dt < 8; dt++) {
            const int col = dt * 8 + cq;
            float v0 = o[dt][half * 2 + 0] * inv;
            float v1 = o[dt][half * 2 + 1] * inv;
            __half h0 = __float2half(v0);
            __half h1 = __float2half(v1);
            *(__half2*)&g_atthi[obase + col] = __halves2half2(h0, h1);
            *(__half2*)&g_attlo[obase + col] = __halves2half2(
                __float2half(v0 - __half2float(h0)),
                __float2half(v1 - __half2float(h1)));
        }
    }
}

// ---------------------------------------------------------------------------
// Launch
// ---------------------------------------------------------------------------
extern "C" void kernel_launch(void* const* d_in, const int* in_sizes, int n_in,
                              void* d_out, int out_size)
{
    const float* x     = (const float*)d_in[0];
    const float* Wqkv  = (const float*)d_in[1];
    const float* Wproj = (const float*)d_in[2];
    const float* bproj = (const float*)d_in[3];
    float* out = (float*)d_out;

    float *qkvp;
    __half *xhi, *wqh, *wph, *athi, *atlo;
    cudaGetSymbolAddress((void**)&qkvp, g_qkv);
    cudaGetSymbolAddress((void**)&xhi,  g_xhi);
    cudaGetSymbolAddress((void**)&wqh,  g_wqkv_hi);
    cudaGetSymbolAddress((void**)&wph,  g_wproj_hi);
    cudaGetSymbolAddress((void**)&athi, g_atthi);
    cudaGetSymbolAddress((void**)&atlo, g_attlo);

    // convert x + weights to fp16
    {
        size_t n4 = (size_t)MTOT * C_DIM / 4;
        round_fp32<<<(unsigned)((n4 + 255) / 256), 256>>>(x, xhi, n4);
        transpose_round<<<dim3(QKV_DIM / 32, C_DIM / 32), dim3(32, 8)>>>(Wqkv, wqh, C_DIM, QKV_DIM);
        transpose_round<<<dim3(C_DIM / 32,  C_DIM / 32), dim3(32, 8)>>>(Wproj, wph, C_DIM, C_DIM);
    }

    const int smem1 = 3 * 20480;   // stage 1 (no A_lo)
    const int smem3 = 3 * 30720;   // stage 3 (2-term)
    cudaFuncSetAttribute(wmma_gemm<false>, cudaFuncAttributeMaxDynamicSharedMemorySize, smem1);
    cudaFuncSetAttribute(wmma_gemm<true>,  cudaFuncAttributeMaxDynamicSharedMemorySize, smem3);
    cudaFuncSetAttribute(win_attn_mma, cudaFuncAttributeMaxDynamicSharedMemorySize, ATT_SMEM);

    // Stage 1: qkv = x @ Wqkv (plain fp16: error attenuated through softmax)
    wmma_gemm<false><<<dim3(QKV_DIM / GBN, MTOT / GBM), 256, smem1>>>(
        xhi, nullptr, wqh, nullptr, qkvp, QKV_DIM);

    // Stage 2: fused MMA attention
    win_attn_mma<<<dim3(LWIN, NHEADS, B_SZ), ATT_THREADS, ATT_SMEM>>>();

    // Stage 3: out = att @ Wproj + bproj (2-term split: last op, not attenuated)
    wmma_gemm<true><<<dim3(C_DIM / GBN, MTOT / GBM), 256, smem3>>>(
        athi, atlo, wph, bproj, out, C_DIM);
}

// round 9
// speedup vs baseline: 5.6540x; 1.2384x over previous
#include <cuda_runtime.h>
#include <cuda_bf16.h>
#include <cuda_fp16.h>
#include <math.h>
#include <stdint.h>

// ---------------------------------------------------------------------------
// WindowedAttention on GB300 (sm_103a chip; ptxas target is base sm_103 so
// tcgen05 unavailable — warp-level mma.sync tensor cores).
// R9: stage 1 plain fp16 GEMM writing fp16 qkv directly;
//     attention all-fp16: QK 1-term, P 2-term, V via ldmatrix.trans;
//     stage 3 fp16 2-term split ((A_hi+A_lo) @ B_hi) -> fp32 out.
// ---------------------------------------------------------------------------

#define C_DIM    768
#define QKV_DIM  2304
#define B_SZ     8
#define H_IMG    80
#define W_IMG    80
#define NTOK     (H_IMG * W_IMG)     // 6400
#define WIN      14
#define NW_WIN   6
#define LWIN     36
#define NWTOK    (WIN * WIN)         // 196
#define NHEADS   12
#define HDIM     64
#define MTOT     (B_SZ * NTOK)       // 51200

// ---------------- scratch (__device__ globals: allocation-free rule) -------
__device__ __half  g_qkvh[(size_t)MTOT * QKV_DIM];     // fp16 qkv
__device__ __half  g_xhi[(size_t)MTOT * C_DIM];
__device__ __half  g_wqkv_hi[(size_t)QKV_DIM * C_DIM]; // [N,K] K-major
__device__ __half  g_wproj_hi[(size_t)C_DIM * C_DIM];  // [N,K] K-major
__device__ __half  g_atthi[(size_t)MTOT * C_DIM];
__device__ __half  g_attlo[(size_t)MTOT * C_DIM];

extern __shared__ char smem_raw[];

// ---------------------------- PTX helpers ----------------------------------
__device__ __forceinline__ uint32_t smem_u32(const void* p) {
    uint32_t a;
    asm("{ .reg .u64 t; cvta.to.shared.u64 t, %1; cvt.u32.u64 %0, t; }"
        : "=r"(a) : "l"(p));
    return a;
}
__device__ __forceinline__ void cp16(uint32_t saddr, const void* g) {
    asm volatile("cp.async.cg.shared.global [%0], [%1], 16;" :: "r"(saddr), "l"(g));
}
__device__ __forceinline__ void cp_commit() { asm volatile("cp.async.commit_group;" ::: "memory"); }
template <int N> __device__ __forceinline__ void cp_wait() {
    asm volatile("cp.async.wait_group %0;" :: "n"(N) : "memory");
}
__device__ __forceinline__ void ldm_x4(uint32_t* r, uint32_t addr) {
    asm volatile("ldmatrix.sync.aligned.m8n8.x4.shared.b16 {%0,%1,%2,%3}, [%4];"
        : "=r"(r[0]), "=r"(r[1]), "=r"(r[2]), "=r"(r[3]) : "r"(addr));
}
__device__ __forceinline__ void ldm_x4_t(uint32_t* r, uint32_t addr) {
    asm volatile("ldmatrix.sync.aligned.m8n8.x4.trans.shared.b16 {%0,%1,%2,%3}, [%4];"
        : "=r"(r[0]), "=r"(r[1]), "=r"(r[2]), "=r"(r[3]) : "r"(addr));
}
// fp16 MMA, fp32 accum
__device__ __forceinline__ void mma16816h(float* d, const uint32_t* a, const uint32_t* b) {
    asm volatile(
        "mma.sync.aligned.m16n8k16.row.col.f32.f16.f16.f32 "
        "{%0,%1,%2,%3}, {%4,%5,%6,%7}, {%8,%9}, {%0,%1,%2,%3};"
        : "+f"(d[0]), "+f"(d[1]), "+f"(d[2]), "+f"(d[3])
        : "r"(a[0]), "r"(a[1]), "r"(a[2]), "r"(a[3]), "r"(b[0]), "r"(b[1]));
}
__device__ __forceinline__ uint32_t pack_f16(float lo, float hi) {
    __half2 h = __floats2half2_rn(lo, hi);
    return *(uint32_t*)&h;
}

// ---------------------------------------------------------------------------
// Warp-MMA GEMM: C[M,N] = A[M,768] @ B[N,768]^T (+ bias), fp16 operands.
// USE_ALO adds (A_lo @ B_hi). HALF_OUT writes __half C (no fp32).
// BM=BN=128, BK=32, 8 warps (2x4), 3-stage cp.async, single sync per chunk.
// ---------------------------------------------------------------------------
#define GBM 128
#define GBN 128
#define GBK 32
#define GNCH (768 / GBK)         // 24
#define ROWB 80                  // smem row stride bytes (32 halves + 8 pad)
#define OFF_ALO 10240

template <bool USE_ALO>
__device__ __forceinline__ void gemm_load_chunk(
    uint32_t buf,
    const __half* __restrict__ Ahi, const __half* __restrict__ Alo,
    const __half* __restrict__ Bhi,
    int rowBase, int colBase, int k0, int tid)
{
    constexpr uint32_t OFF_BHI_T = USE_ALO ? 20480u : 10240u;
#pragma unroll
    for (int it = 0; it < 2; it++) {
        int t = tid + it * 256;           // 0..511
        int r = t >> 2;                   // row 0..127
        int c = t & 3;                    // 16B unit 0..3
        uint32_t soff = (uint32_t)(r * ROWB + c * 16);
        size_t ga = (size_t)(rowBase + r) * 768 + k0 + c * 8;
        size_t gb = (size_t)(colBase + r) * 768 + k0 + c * 8;
        cp16(buf + soff, Ahi + ga);
        if (USE_ALO) cp16(buf + OFF_ALO + soff, Alo + ga);
        cp16(buf + OFF_BHI_T + soff, Bhi + gb);
    }
    cp_commit();
}

template <bool USE_ALO, bool HALF_OUT>
__global__ void __launch_bounds__(256)
wmma_gemm(const __half* __restrict__ Ahi, const __half* __restrict__ Alo,
          const __half* __restrict__ Bhi,
          const float* __restrict__ bias, void* __restrict__ Cv, int N)
{
    constexpr uint32_t OFF_BHI_T = USE_ALO ? 20480u : 10240u;
    constexpr uint32_t STG = USE_ALO ? 30720u : 20480u;

    const uint32_t sb = smem_u32(smem_raw);
    const int tid   = threadIdx.x;
    const int lane  = tid & 31;
    const int wid   = tid >> 5;
    const int warpM = wid >> 2;
    const int warpN = wid & 3;
    const int rowBase = blockIdx.y * GBM;
    const int colBase = blockIdx.x * GBN;

    float acc[4][4][4];
#pragma unroll
    for (int i = 0; i < 4; i++)
#pragma unroll
        for (int j = 0; j < 4; j++)
#pragma unroll
            for (int e = 0; e < 4; e++) acc[i][j][e] = 0.f;

    const uint32_t a_lane = (uint32_t)((warpM * 64 + (lane & 15)) * ROWB + (lane >> 4) * 16);
    const uint32_t b_lane = (uint32_t)((warpN * 32 + ((lane & 7) | ((lane >> 4) << 3))) * ROWB
                                       + ((lane >> 3) & 1) * 16);

    gemm_load_chunk<USE_ALO>(sb,       Ahi, Alo, Bhi, rowBase, colBase, 0,   tid);
    gemm_load_chunk<USE_ALO>(sb + STG, Ahi, Alo, Bhi, rowBase, colBase, GBK, tid);

    for (int ch = 0; ch < GNCH; ch++) {
        if (ch < GNCH - 1) cp_wait<1>(); else cp_wait<0>();
        __syncthreads();
        if (ch + 2 < GNCH)
            gemm_load_chunk<USE_ALO>(sb + (uint32_t)((ch + 2) % 3) * STG,
                                     Ahi, Alo, Bhi, rowBase, colBase,
                                     (ch + 2) * GBK, tid);
        const uint32_t buf = sb + (uint32_t)(ch % 3) * STG;

#pragma unroll
        for (int k16 = 0; k16 < 2; k16++) {
            const uint32_t kb = (uint32_t)(k16 * 32);
            uint32_t ah[4][4], al[4][4];
#pragma unroll
            for (int mt = 0; mt < 4; mt++) {
                uint32_t ao = buf + a_lane + kb + (uint32_t)(mt * 16 * ROWB);
                ldm_x4(ah[mt], ao);
                if (USE_ALO) ldm_x4(al[mt], ao + OFF_ALO);
            }
            uint32_t bh[2][4];
#pragma unroll
            for (int half = 0; half < 2; half++) {
                uint32_t bo = buf + b_lane + kb + (uint32_t)(half * 16 * ROWB);
                ldm_x4(bh[half], bo + OFF_BHI_T);
            }
#pragma unroll
            for (int mt = 0; mt < 4; mt++)
#pragma unroll
                for (int nt = 0; nt < 4; nt++) {
                    const uint32_t* bhf = &bh[nt >> 1][(nt & 1) * 2];
                    mma16816h(acc[mt][nt], ah[mt], bhf);
                    if (USE_ALO) mma16816h(acc[mt][nt], al[mt], bhf);
                }
        }
    }

#pragma unroll
    for (int mt = 0; mt < 4; mt++) {
        const int row0 = rowBase + warpM * 64 + mt * 16 + (lane >> 2);
#pragma unroll
        for (int nt = 0; nt < 4; nt++) {
            const int col = colBase + warpN * 32 + nt * 8 + (lane & 3) * 2;
            float b0 = 0.f, b1 = 0.f;
            if (bias != nullptr) { b0 = bias[col]; b1 = bias[col + 1]; }
            if (HALF_OUT) {
                __half* Ch = (__half*)Cv;
                *(__half2*)&Ch[(size_t)row0 * N + col] =
                    __floats2half2_rn(acc[mt][nt][0] + b0, acc[mt][nt][1] + b1);
                *(__half2*)&Ch[(size_t)(row0 + 8) * N + col] =
                    __floats2half2_rn(acc[mt][nt][2] + b0, acc[mt][nt][3] + b1);
            } else {
                float* C = (float*)Cv;
                *(float2*)&C[(size_t)row0 * N + col] =
                    make_float2(acc[mt][nt][0] + b0, acc[mt][nt][1] + b1);
                *(float2*)&C[(size_t)(row0 + 8) * N + col] =
                    make_float2(acc[mt][nt][2] + b0, acc[mt][nt][3] + b1);
            }
        }
    }
}

// ---------------------------------------------------------------------------
// fp32 -> fp16 round (for x)
// ---------------------------------------------------------------------------
__global__ void round_fp32(const float* __restrict__ src,
                           __half* __restrict__ hi, size_t n4)
{
    size_t i = (size_t)blockIdx.x * blockDim.x + threadIdx.x;
    if (i >= n4) return;
    float4 v = ((const float4*)src)[i];
    __half2* hp = (__half2*)hi;
    hp[i * 2 + 0] = __halves2half2(__float2half(v.x), __float2half(v.y));
    hp[i * 2 + 1] = __halves2half2(__float2half(v.z), __float2half(v.w));
}

// ---------------------------------------------------------------------------
// W [K,N] row-major -> [N,K] K-major fp16 (transpose + round)
// ---------------------------------------------------------------------------
__global__ void transpose_round(const float* __restrict__ W,
                                __half* __restrict__ hi, int K, int N)
{
    __shared__ float t[32][33];
    int n0 = blockIdx.x * 32, k0 = blockIdx.y * 32;
    for (int r = threadIdx.y; r < 32; r += 8)
        t[r][threadIdx.x] = W[(size_t)(k0 + r) * N + n0 + threadIdx.x];
    __syncthreads();
    for (int r = threadIdx.y; r < 32; r += 8) {
        float v = t[threadIdx.x][r];
        hi[(size_t)(n0 + r) * K + k0 + threadIdx.x] = __float2half(v);
    }
}

// ---------------------------------------------------------------------------
// Fused MMA attention, all fp16. Grid (LWIN, NHEADS, B), 13 warps (416 thr).
// Q,K,V staged in smem as [row 208][64] fp16, row stride 144B (cp.async).
// QK: 1-term fp16 MMA, logits scaled by 0.125 in fp32 post-MMA.
// Softmax: two-pass exact (pass1 max, pass2 exp + P@V).
// PV: P 2-term fp16 A-frags; V B-frags via ldmatrix.x4.trans on row-major V.
// ---------------------------------------------------------------------------
#define AROW   144
#define SQ_O   0
#define SK_O   29952
#define SV_O   59904
#define ATT_SMEM 89856
#define ATT_THREADS 416

__global__ void __launch_bounds__(ATT_THREADS)
win_attn_mma()
{
    const uint32_t sb = smem_u32(smem_raw);
    const int l    = blockIdx.x;
    const int head = blockIdx.y;
    const int b    = blockIdx.z;
    const int wy   = l / NW_WIN;
    const int wx   = l % NW_WIN;
    const int tid  = threadIdx.x;
    const int lane = tid & 31;
    const int w    = tid >> 5;       // 0..12

    // ---- stage Q,K,V (fp16) into smem; zero-fill pad rows ----
#pragma unroll
    for (int it = 0; it < 12; it++) {
        int idx = tid + it * ATT_THREADS;   // 0..4991
        int arr = idx / 1664;               // 0=Q 1=K 2=V
        int rem = idx - arr * 1664;
        int row = rem >> 3;                 // 0..207
        int c   = rem & 7;                  // 16B unit
        uint32_t soff = (uint32_t)(arr * SK_O + row * AROW + c * 16);
        int rr = row / WIN, cc = row % WIN;
        int hh = wy * WIN + rr, ww = wx * WIN + cc;
        if (row < NWTOK && hh < H_IMG && ww < W_IMG) {
            size_t gbase = ((size_t)(b * NTOK + hh * W_IMG + ww)) * QKV_DIM
                           + (size_t)head * HDIM + (size_t)arr * C_DIM + c * 8;
            cp16(sb + soff, g_qkvh + gbase);
        } else {
            *(uint4*)(smem_raw + soff) = make_uint4(0, 0, 0, 0);
        }
    }
    cp_commit();
    cp_wait<0>();
    __syncthreads();

    // ---- fragment lane addresses ----
    const uint32_t a_lane  = sb + SQ_O
        + (uint32_t)((w * 16 + (lane & 15)) * AROW + (lane >> 4) * 16);
    const uint32_t kb_lane = sb + SK_O
        + (uint32_t)((((lane & 7) | ((lane >> 4) << 3))) * AROW + ((lane >> 3) & 1) * 16);
    const uint32_t vb_lane = sb + SV_O
        + (uint32_t)(((((lane >> 3) & 1) * 8 + (lane & 7))) * AROW + (lane >> 4) * 16);

    uint32_t qa[4][4];
#pragma unroll
    for (int kt = 0; kt < 4; kt++) ldm_x4(qa[kt], a_lane + kt * 32);

    const int cq = 2 * (lane & 3);

    // ---- pass 1: row max ----
    float m0 = -1e30f, m1 = -1e30f;
    for (int t = 0; t < 13; t++) {
        float s0[4] = {0.f, 0.f, 0.f, 0.f}, s1[4] = {0.f, 0.f, 0.f, 0.f};
#pragma unroll
        for (int kt = 0; kt < 4; kt++) {
            uint32_t kb[4];
            ldm_x4(kb, kb_lane + (uint32_t)(t * 16 * AROW + kt * 32));
            mma16816h(s0, qa[kt], &kb[0]);
            mma16816h(s1, qa[kt], &kb[2]);
        }
        int j0 = t * 16 + cq;
        int j1 = j0 + 8;
        if (j0     < NWTOK) { m0 = fmaxf(m0, s0[0]); m1 = fmaxf(m1, s0[2]); }
        if (j0 + 1 < NWTOK) { m0 = fmaxf(m0, s0[1]); m1 = fmaxf(m1, s0[3]); }
        if (j1     < NWTOK) { m0 = fmaxf(m0, s1[0]); m1 = fmaxf(m1, s1[2]); }
        if (j1 + 1 < NWTOK) { m0 = fmaxf(m0, s1[1]); m1 = fmaxf(m1, s1[3]); }
    }
    // maxes computed on unscaled logits; scale once (0.125 > 0 so order-safe)
    m0 *= 0.125f;  m1 *= 0.125f;
#pragma unroll
    for (int off = 1; off <= 2; off <<= 1) {
        m0 = fmaxf(m0, __shfl_xor_sync(0xffffffffu, m0, off));
        m1 = fmaxf(m1, __shfl_xor_sync(0xffffffffu, m1, off));
    }

    // ---- pass 2: recompute S, P = exp(s*0.125 - m), O += P@V ----
    float o[8][4];
#pragma unroll
    for (int i = 0; i < 8; i++)
#pragma unroll
        for (int e = 0; e < 4; e++) o[i][e] = 0.f;
    float sum0 = 0.f, sum1 = 0.f;

    for (int t = 0; t < 13; t++) {
        float s0[4] = {0.f, 0.f, 0.f, 0.f}, s1[4] = {0.f, 0.f, 0.f, 0.f};
#pragma unroll
        for (int kt = 0; kt < 4; kt++) {
            uint32_t kb[4];
            ldm_x4(kb, kb_lane + (uint32_t)(t * 16 * AROW + kt * 32));
            mma16816h(s0, qa[kt], &kb[0]);
            mma16816h(s1, qa[kt], &kb[2]);
        }
        int j0 = t * 16 + cq;
        int j1 = j0 + 8;
        float p0 = (j0     < NWTOK) ? __expf(s0[0] * 0.125f - m0) : 0.f;
        float p1 = (j0 + 1 < NWTOK) ? __expf(s0[1] * 0.125f - m0) : 0.f;
        float p2 = (j0     < NWTOK) ? __expf(s0[2] * 0.125f - m1) : 0.f;
        float p3 = (j0 + 1 < NWTOK) ? __expf(s0[3] * 0.125f - m1) : 0.f;
        float u0 = (j1     < NWTOK) ? __expf(s1[0] * 0.125f - m0) : 0.f;
        float u1 = (j1 + 1 < NWTOK) ? __expf(s1[1] * 0.125f - m0) : 0.f;
        float u2 = (j1     < NWTOK) ? __expf(s1[2] * 0.125f - m1) : 0.f;
        float u3 = (j1 + 1 < NWTOK) ? __expf(s1[3] * 0.125f - m1) : 0.f;
        sum0 += p0 + p1 + u0 + u1;
        sum1 += p2 + p3 + u2 + u3;

        // P hi/lo fp16 A-fragments
        uint32_t pah[4], pal[4];
        pah[0] = pack_f16(p0, p1);  pah[1] = pack_f16(p2, p3);
        pah[2] = pack_f16(u0, u1);  pah[3] = pack_f16(u2, u3);
        {
            float q0 = __half2float(__low2half(*(__half2*)&pah[0]));
            float q1 = __half2float(__high2half(*(__half2*)&pah[0]));
            float q2 = __half2float(__low2half(*(__half2*)&pah[1]));
            float q3 = __half2float(__high2half(*(__half2*)&pah[1]));
            float r0 = __half2float(__low2half(*(__half2*)&pah[2]));
            float r1 = __half2float(__high2half(*(__half2*)&pah[2]));
            float r2 = __half2float(__low2half(*(__half2*)&pah[3]));
            float r3 = __half2float(__high2half(*(__half2*)&pah[3]));
            pal[0] = pack_f16(p0 - q0, p1 - q1);
            pal[1] = pack_f16(p2 - q2, p3 - q3);
            pal[2] = pack_f16(u0 - r0, u1 - r1);
            pal[3] = pack_f16(u2 - r2, u3 - r3);
        }

#pragma unroll
        for (int dg = 0; dg < 4; dg++) {
            uint32_t vb[4];
            ldm_x4_t(vb, vb_lane + (uint32_t)(t * 16 * AROW + dg * 32));
            mma16816h(o[dg * 2 + 0], pah, &vb[0]);
            mma16816h(o[dg * 2 + 0], pal, &vb[0]);
            mma16816h(o[dg * 2 + 1], pah, &vb[2]);
            mma16816h(o[dg * 2 + 1], pal, &vb[2]);
        }
    }
#pragma unroll
    for (int off = 1; off <= 2; off <<= 1) {
        sum0 += __shfl_xor_sync(0xffffffffu, sum0, off);
        sum1 += __shfl_xor_sync(0xffffffffu, sum1, off);
    }
    const float inv0 = 1.f / sum0;
    const float inv1 = 1.f / sum1;

    // ---- epilogue: O/sum -> g_atthi/lo (fp16 hi/lo split) ----
    const int r0 = w * 16 + (lane >> 2);
#pragma unroll
    for (int half = 0; half < 2; half++) {
        const int row = r0 + half * 8;
        if (row >= NWTOK) continue;
        const int rr = row / WIN, cc = row % WIN;
        const int hh = wy * WIN + rr, ww = wx * WIN + cc;
        if (hh >= H_IMG || ww >= W_IMG) continue;
        const float inv = half ? inv1 : inv0;
        const size_t obase = ((size_t)(b * NTOK + hh * W_IMG + ww)) * C_DIM
                             + (size_t)head * HDIM;
#pragma unroll
        for (int dt = 0; dt < 8; dt++) {
            const int col = dt * 8 + cq;
            float v0 = o[dt][half * 2 + 0] * inv;
            float v1 = o[dt][half * 2 + 1] * inv;
            __half h0 = __float2half(v0);
            __half h1 = __float2half(v1);
            *(__half2*)&g_atthi[obase + col] = __halves2half2(h0, h1);
            *(__half2*)&g_attlo[obase + col] = __halves2half2(
                __float2half(v0 - __half2float(h0)),
                __float2half(v1 - __half2float(h1)));
        }
    }
}

// ---------------------------------------------------------------------------
// Launch
// ---------------------------------------------------------------------------
extern "C" void kernel_launch(void* const* d_in, const int* in_sizes, int n_in,
                              void* d_out, int out_size)
{
    const float* x     = (const float*)d_in[0];
    const float* Wqkv  = (const float*)d_in[1];
    const float* Wproj = (const float*)d_in[2];
    const float* bproj = (const float*)d_in[3];
    float* out = (float*)d_out;

    __half *qkvh, *xhi, *wqh, *wph, *athi, *atlo;
    cudaGetSymbolAddress((void**)&qkvh, g_qkvh);
    cudaGetSymbolAddress((void**)&xhi,  g_xhi);
    cudaGetSymbolAddress((void**)&wqh,  g_wqkv_hi);
    cudaGetSymbolAddress((void**)&wph,  g_wproj_hi);
    cudaGetSymbolAddress((void**)&athi, g_atthi);
    cudaGetSymbolAddress((void**)&atlo, g_attlo);

    // convert x + weights to fp16
    {
        size_t n4 = (size_t)MTOT * C_DIM / 4;
        round_fp32<<<(unsigned)((n4 + 255) / 256), 256>>>(x, xhi, n4);
        transpose_round<<<dim3(QKV_DIM / 32, C_DIM / 32), dim3(32, 8)>>>(Wqkv, wqh, C_DIM, QKV_DIM);
        transpose_round<<<dim3(C_DIM / 32,  C_DIM / 32), dim3(32, 8)>>>(Wproj, wph, C_DIM, C_DIM);
    }

    const int smem1 = 3 * 20480;   // stage 1 (no A_lo)
    const int smem3 = 3 * 30720;   // stage 3 (2-term)
    cudaFuncSetAttribute((const void*)wmma_gemm<false, true>,
                         cudaFuncAttributeMaxDynamicSharedMemorySize, smem1);
    cudaFuncSetAttribute((const void*)wmma_gemm<true, false>,
                         cudaFuncAttributeMaxDynamicSharedMemorySize, smem3);
    cudaFuncSetAttribute((const void*)win_attn_mma,
                         cudaFuncAttributeMaxDynamicSharedMemorySize, ATT_SMEM);

    // Stage 1: qkv(fp16) = x @ Wqkv  (plain fp16; logit error attenuated)
    wmma_gemm<false, true><<<dim3(QKV_DIM / GBN, MTOT / GBM), 256, smem1>>>(
        xhi, nullptr, wqh, nullptr, (void*)qkvh, QKV_DIM);

    // Stage 2: fused all-fp16 MMA attention
    win_attn_mma<<<dim3(LWIN, NHEADS, B_SZ), ATT_THREADS, ATT_SMEM>>>();

    // Stage 3: out = att @ Wproj + bproj (2-term split, fp32 out)
    wmma_gemm<true, false><<<dim3(C_DIM / GBN, MTOT / GBM), 256, smem3>>>(
        athi, atlo, wph, bproj, (void*)out, C_DIM);
}